// round 2
// baseline (speedup 1.0000x reference)
#include <cuda_runtime.h>
#include <cstdint>

#define BATCH 8
#define CH    512
#define NTOK  1024
#define NH    8
#define HD    64
#define TC    1536
#define ATT_SCALE 0.125f

// Scratch (allocation-free rule: __device__ globals)
__device__ float g_qkv[3 * BATCH * NH * NTOK * HD];   // [s][b][h][n][d]
__device__ float g_attn[BATCH * NTOK * CH];           // [b][n][c]

typedef unsigned long long u64;

__device__ __forceinline__ u64 pk2(float lo, float hi) {
    u64 r; asm("mov.b64 %0, {%1,%2};" : "=l"(r) : "f"(lo), "f"(hi)); return r;
}
__device__ __forceinline__ void upk2(u64 v, float& lo, float& hi) {
    asm("mov.b64 {%0,%1}, %2;" : "=f"(lo), "=f"(hi) : "l"(v));
}
__device__ __forceinline__ void fma2(u64& c, u64 a, u64 b) {
    asm("fma.rn.f32x2 %0, %1, %2, %0;" : "+l"(c) : "l"(a), "l"(b));
}
__device__ __forceinline__ void mul2(u64& c, u64 a) {
    asm("mul.rn.f32x2 %0, %0, %1;" : "+l"(c) : "l"(a));
}

// ---------------------------------------------------------------------------
// Kernel 1: QKV GEMM.  out[b, n, j] = sum_k x[b,k,n] * w_qkv[k,j] + b_qkv[j]
// scattered into g_qkv[s][b][h][n][d] with j = s*512 + h*64 + d.
// Tile: BM=128 (tokens) x BN=128 (j) x BK=16, 256 threads, 8x8 per thread.
// ---------------------------------------------------------------------------
__global__ void __launch_bounds__(256, 1) qkv_kernel(
    const float* __restrict__ x, const float* __restrict__ w,
    const float* __restrict__ bias)
{
    __shared__ u64   As2[16][128];   // (a,a) duplicated pairs, 16 KB
    __shared__ float Bs[16][128];    // 8 KB

    const int b  = blockIdx.z;
    const int m0 = blockIdx.y * 128;
    const int j0 = blockIdx.x * 128;
    const int tid = threadIdx.x;
    const int tx = tid & 15, ty = tid >> 4;

    const float* xA = x + b * CH * NTOK;   // x[b][k][m], m contiguous

    u64 acc[8][4];
#pragma unroll
    for (int i = 0; i < 8; i++)
#pragma unroll
        for (int j = 0; j < 4; j++) acc[i][j] = 0ull;

    const int lk  = tid >> 4;     // k row within tile 0..15
    const int lmx = tid & 15;     // strided m loader lane

    for (int k0 = 0; k0 < CH; k0 += 16) {
        // A tile: As2[kk][m] = (x[b][k0+kk][m0+m], dup)
        const float* ap = xA + (k0 + lk) * NTOK + m0 + lmx;
#pragma unroll
        for (int q = 0; q < 8; q++) {
            float v = ap[q * 16];
            As2[lk][lmx + q * 16] = pk2(v, v);
        }
        // B tile: Bs[kk][j]
        const float* bp = w + (k0 + lk) * TC + j0 + lmx * 8;
        *(float4*)&Bs[lk][lmx * 8]     = *(const float4*)bp;
        *(float4*)&Bs[lk][lmx * 8 + 4] = *(const float4*)(bp + 4);
        __syncthreads();
#pragma unroll
        for (int kk = 0; kk < 16; kk++) {
            u64 a[8];
#pragma unroll
            for (int i = 0; i < 8; i++) a[i] = As2[kk][ty * 8 + i];
            ulonglong2 b0 = *(const ulonglong2*)&Bs[kk][tx * 8];
            ulonglong2 b1 = *(const ulonglong2*)&Bs[kk][tx * 8 + 4];
            u64 bp4[4] = { b0.x, b0.y, b1.x, b1.y };
#pragma unroll
            for (int i = 0; i < 8; i++)
#pragma unroll
                for (int j = 0; j < 4; j++) fma2(acc[i][j], a[i], bp4[j]);
        }
        __syncthreads();
    }

    // epilogue: j block of 8 stays inside one (s, h)
    const int j  = j0 + tx * 8;
    const int s  = j >> 9;
    const int h  = (j >> 6) & (NH - 1);
    const int d0 = j & (HD - 1);
    float4 bv0 = *(const float4*)(bias + j);
    float4 bv1 = *(const float4*)(bias + j + 4);
    float* dst = g_qkv + (((s * BATCH + b) * NH + h) * NTOK + m0) * HD + d0;
#pragma unroll
    for (int i = 0; i < 8; i++) {
        float f[8];
#pragma unroll
        for (int jp = 0; jp < 4; jp++) upk2(acc[i][jp], f[jp * 2], f[jp * 2 + 1]);
        float* row = dst + (ty * 8 + i) * HD;
        *(float4*)row       = make_float4(f[0] + bv0.x, f[1] + bv0.y, f[2] + bv0.z, f[3] + bv0.w);
        *(float4*)(row + 4) = make_float4(f[4] + bv1.x, f[5] + bv1.y, f[6] + bv1.z, f[7] + bv1.w);
    }
}

// ---------------------------------------------------------------------------
// Kernel 2: Flash attention. One CTA per (b*H+h, 128-row block of N).
// smem: Qs[128][68] (pre-scaled), Kt[64][128] (transposed), Vs[128][68],
//       Ps[128][128].  Online softmax state in registers (replicated per tx).
// ---------------------------------------------------------------------------
#define QS_STRIDE 68
#define VS_STRIDE 68
#define ATTN_SMEM ((128*QS_STRIDE + 64*128 + 128*VS_STRIDE + 128*128) * 4)

__global__ void __launch_bounds__(256, 1) attn_kernel()
{
    extern __shared__ float smem[];
    float* Qs = smem;                               // [128][68]
    float* Kt = Qs + 128 * QS_STRIDE;               // [64][128]
    float* Vs = Kt + 64 * 128;                      // [128][68]
    float* Ps = Vs + 128 * VS_STRIDE;               // [128][128]

    const int bh = blockIdx.x;          // b*NH + h
    const int m0 = blockIdx.y * 128;
    const int tid = threadIdx.x;
    const int tx = tid & 15, ty = tid >> 4;

    const float* qg = g_qkv + bh * (NTOK * HD);
    const float* kg = g_qkv + (BATCH * NH + bh) * (NTOK * HD);
    const float* vg = g_qkv + (2 * BATCH * NH + bh) * (NTOK * HD);

    // load Q block (pre-scaled by 1/sqrt(D))
    {
        const int r  = tid >> 1;
        const int dh = (tid & 1) * 32;
        const float* src = qg + (m0 + r) * HD + dh;
#pragma unroll
        for (int q = 0; q < 8; q++) {
            float4 v = *(const float4*)(src + q * 4);
            v.x *= ATT_SCALE; v.y *= ATT_SCALE; v.z *= ATT_SCALE; v.w *= ATT_SCALE;
            *(float4*)&Qs[r * QS_STRIDE + dh + q * 4] = v;
        }
    }

    float mreg[8], lreg[8];
    u64 o2[8][2];
#pragma unroll
    for (int i = 0; i < 8; i++) {
        mreg[i] = -1e30f; lreg[i] = 0.f;
        o2[i][0] = 0ull; o2[i][1] = 0ull;
    }

    for (int n0 = 0; n0 < NTOK; n0 += 128) {
        __syncthreads();   // protect Kt/Vs/Ps vs previous iteration's PV reads
        {
            const int jj = tid >> 1;
            const int dh = (tid & 1) * 32;
            const float* ks = kg + (n0 + jj) * HD + dh;
            const float* vs = vg + (n0 + jj) * HD + dh;
#pragma unroll
            for (int q = 0; q < 8; q++) {
                float4 kv = *(const float4*)(ks + q * 4);
                Kt[(dh + q * 4 + 0) * 128 + jj] = kv.x;
                Kt[(dh + q * 4 + 1) * 128 + jj] = kv.y;
                Kt[(dh + q * 4 + 2) * 128 + jj] = kv.z;
                Kt[(dh + q * 4 + 3) * 128 + jj] = kv.w;
                *(float4*)&Vs[jj * VS_STRIDE + dh + q * 4] = *(const float4*)(vs + q * 4);
            }
        }
        __syncthreads();

        // S = Q K^T  (rows ty*8+i, cols tx*8+jj, pairs over jj)
        u64 s2[8][4];
#pragma unroll
        for (int i = 0; i < 8; i++)
#pragma unroll
            for (int j = 0; j < 4; j++) s2[i][j] = 0ull;

        for (int d = 0; d < HD; d++) {
            ulonglong2 k0 = *(const ulonglong2*)&Kt[d * 128 + tx * 8];
            ulonglong2 k1 = *(const ulonglong2*)&Kt[d * 128 + tx * 8 + 4];
#pragma unroll
            for (int i = 0; i < 8; i++) {
                float qv = Qs[(ty * 8 + i) * QS_STRIDE + d];
                u64 qq = pk2(qv, qv);
                fma2(s2[i][0], qq, k0.x);
                fma2(s2[i][1], qq, k0.y);
                fma2(s2[i][2], qq, k1.x);
                fma2(s2[i][3], qq, k1.y);
            }
        }

        // online softmax (reductions across the 16 tx lanes sharing each row)
#pragma unroll
        for (int i = 0; i < 8; i++) {
            float sv[8];
#pragma unroll
            for (int jp = 0; jp < 4; jp++) upk2(s2[i][jp], sv[jp * 2], sv[jp * 2 + 1]);
            float mx = sv[0];
#pragma unroll
            for (int jj = 1; jj < 8; jj++) mx = fmaxf(mx, sv[jj]);
#pragma unroll
            for (int sft = 8; sft > 0; sft >>= 1)
                mx = fmaxf(mx, __shfl_xor_sync(0xffffffffu, mx, sft));
            float newm  = fmaxf(mreg[i], mx);
            float alpha = __expf(mreg[i] - newm);
            mreg[i] = newm;
            float rs = 0.f;
            float e[8];
#pragma unroll
            for (int jj = 0; jj < 8; jj++) { e[jj] = __expf(sv[jj] - newm); rs += e[jj]; }
            *(float4*)&Ps[(ty * 8 + i) * 128 + tx * 8]     = make_float4(e[0], e[1], e[2], e[3]);
            *(float4*)&Ps[(ty * 8 + i) * 128 + tx * 8 + 4] = make_float4(e[4], e[5], e[6], e[7]);
#pragma unroll
            for (int sft = 8; sft > 0; sft >>= 1)
                rs += __shfl_xor_sync(0xffffffffu, rs, sft);
            lreg[i] = lreg[i] * alpha + rs;
            u64 ap = pk2(alpha, alpha);
            mul2(o2[i][0], ap);
            mul2(o2[i][1], ap);
        }
        __syncthreads();

        // O += P V  (thread owns rows ty*8+i, d-cols tx*4..tx*4+3)
        for (int j = 0; j < 128; j++) {
            ulonglong2 vv = *(const ulonglong2*)&Vs[j * VS_STRIDE + tx * 4];
#pragma unroll
            for (int i = 0; i < 8; i++) {
                float p = Ps[(ty * 8 + i) * 128 + j];
                u64 pp = pk2(p, p);
                fma2(o2[i][0], pp, vv.x);
                fma2(o2[i][1], pp, vv.y);
            }
        }
    }

    // normalize + write to g_attn[b][n][h*64+d]
    const int b = bh >> 3;
    const int h = bh & 7;
    float* outp = g_attn + (b * NTOK + m0) * CH + h * HD + tx * 4;
#pragma unroll
    for (int i = 0; i < 8; i++) {
        float inv = 1.0f / lreg[i];
        float f0, f1, f2, f3;
        upk2(o2[i][0], f0, f1);
        upk2(o2[i][1], f2, f3);
        *(float4*)(outp + (ty * 8 + i) * CH) =
            make_float4(f0 * inv, f1 * inv, f2 * inv, f3 * inv);
    }
}

// ---------------------------------------------------------------------------
// Kernel 3: Proj GEMM.  out[b, c_out, n] = sum_c g_attn[b,n,c] * w_proj[c,c_out]
//                       + b_proj[c_out]   (output in (B, C, N) layout)
// ---------------------------------------------------------------------------
__global__ void __launch_bounds__(256, 1) proj_kernel(
    const float* __restrict__ w, const float* __restrict__ bias,
    float* __restrict__ out)
{
    __shared__ u64   As2[16][128];
    __shared__ float Bs[16][128];

    const int b  = blockIdx.z;
    const int m0 = blockIdx.y * 128;
    const int j0 = blockIdx.x * 128;
    const int tid = threadIdx.x;
    const int tx = tid & 15, ty = tid >> 4;

    const float* A = g_attn + b * NTOK * CH;   // row-major [n][c]

    u64 acc[8][4];
#pragma unroll
    for (int i = 0; i < 8; i++)
#pragma unroll
        for (int j = 0; j < 4; j++) acc[i][j] = 0ull;

    const int lm  = tid >> 1;
    const int lkh = (tid & 1) * 8;
    const int lk = tid >> 4, lj = (tid & 15) * 8;

    for (int k0 = 0; k0 < CH; k0 += 16) {
        const float* ap = A + (m0 + lm) * CH + k0 + lkh;
        float4 a0 = *(const float4*)ap;
        float4 a1 = *(const float4*)(ap + 4);
        As2[lkh + 0][lm] = pk2(a0.x, a0.x);
        As2[lkh + 1][lm] = pk2(a0.y, a0.y);
        As2[lkh + 2][lm] = pk2(a0.z, a0.z);
        As2[lkh + 3][lm] = pk2(a0.w, a0.w);
        As2[lkh + 4][lm] = pk2(a1.x, a1.x);
        As2[lkh + 5][lm] = pk2(a1.y, a1.y);
        As2[lkh + 6][lm] = pk2(a1.z, a1.z);
        As2[lkh + 7][lm] = pk2(a1.w, a1.w);
        const float* bp = w + (k0 + lk) * CH + j0 + lj;
        *(float4*)&Bs[lk][lj]     = *(const float4*)bp;
        *(float4*)&Bs[lk][lj + 4] = *(const float4*)(bp + 4);
        __syncthreads();
#pragma unroll
        for (int kk = 0; kk < 16; kk++) {
            u64 a[8];
#pragma unroll
            for (int i = 0; i < 8; i++) a[i] = As2[kk][ty * 8 + i];
            ulonglong2 b0 = *(const ulonglong2*)&Bs[kk][tx * 8];
            ulonglong2 b1 = *(const ulonglong2*)&Bs[kk][tx * 8 + 4];
            u64 bp4[4] = { b0.x, b0.y, b1.x, b1.y };
#pragma unroll
            for (int i = 0; i < 8; i++)
#pragma unroll
                for (int j = 0; j < 4; j++) fma2(acc[i][j], a[i], bp4[j]);
        }
        __syncthreads();
    }

    // epilogue: out[b][j][m] (column of tokens is contiguous)
    float4 bv0 = *(const float4*)(bias + j0 + tx * 8);
    float4 bv1 = *(const float4*)(bias + j0 + tx * 8 + 4);
    float bb[8] = { bv0.x, bv0.y, bv0.z, bv0.w, bv1.x, bv1.y, bv1.z, bv1.w };
    float f[8][8];
#pragma unroll
    for (int i = 0; i < 8; i++)
#pragma unroll
        for (int jp = 0; jp < 4; jp++) upk2(acc[i][jp], f[i][jp * 2], f[i][jp * 2 + 1]);
    float* ob = out + b * CH * NTOK + (j0 + tx * 8) * NTOK + m0 + ty * 8;
#pragma unroll
    for (int jj = 0; jj < 8; jj++) {
        *(float4*)(ob + jj * NTOK) =
            make_float4(f[0][jj] + bb[jj], f[1][jj] + bb[jj],
                        f[2][jj] + bb[jj], f[3][jj] + bb[jj]);
        *(float4*)(ob + jj * NTOK + 4) =
            make_float4(f[4][jj] + bb[jj], f[5][jj] + bb[jj],
                        f[6][jj] + bb[jj], f[7][jj] + bb[jj]);
    }
}

// ---------------------------------------------------------------------------
extern "C" void kernel_launch(void* const* d_in, const int* in_sizes, int n_in,
                              void* d_out, int out_size)
{
    const float* x      = (const float*)d_in[0];
    const float* w_qkv  = (const float*)d_in[1];
    const float* b_qkv  = (const float*)d_in[2];
    const float* w_proj = (const float*)d_in[3];
    const float* b_proj = (const float*)d_in[4];
    float* out = (float*)d_out;

    cudaFuncSetAttribute(attn_kernel,
                         cudaFuncAttributeMaxDynamicSharedMemorySize, ATTN_SMEM);

    qkv_kernel<<<dim3(TC / 128, NTOK / 128, BATCH), 256>>>(x, w_qkv, b_qkv);
    attn_kernel<<<dim3(BATCH * NH, NTOK / 128), 256, ATTN_SMEM>>>();
    proj_kernel<<<dim3(CH / 128, NTOK / 128, BATCH), 256>>>(w_proj, b_proj, out);
}

// round 7
// speedup vs baseline: 1.3214x; 1.3214x over previous
#include <cuda_runtime.h>
#include <cuda_bf16.h>
#include <cstdint>

#define BATCH 8
#define CH    512
#define NTOK  1024
#define NH    8
#define HD    64
#define TC    1536
#define ATT_SCALE 0.125f

// Scratch (allocation-free rule: __device__ globals)
__device__ float g_qkv[3 * BATCH * NH * NTOK * HD];   // [s][b][h][n][d]
__device__ float g_attn[BATCH * NTOK * CH];           // [b][n][c]

// bf16 hi/lo split scratch (original layouts; 16B-aligned for int4 access)
__device__ __align__(16) __nv_bfloat16 g_xh[BATCH * CH * NTOK];  // [b][k][m]
__device__ __align__(16) __nv_bfloat16 g_xl[BATCH * CH * NTOK];
__device__ __align__(16) __nv_bfloat16 g_wh[CH * TC];            // [k][j]
__device__ __align__(16) __nv_bfloat16 g_wl[CH * TC];

typedef unsigned long long u64;

__device__ __forceinline__ u64 pk2(float lo, float hi) {
    u64 r; asm("mov.b64 %0, {%1,%2};" : "=l"(r) : "f"(lo), "f"(hi)); return r;
}
__device__ __forceinline__ void upk2(u64 v, float& lo, float& hi) {
    asm("mov.b64 {%0,%1}, %2;" : "=f"(lo), "=f"(hi) : "l"(v));
}
__device__ __forceinline__ void fma2(u64& c, u64 a, u64 b) {
    asm("fma.rn.f32x2 %0, %1, %2, %0;" : "+l"(c) : "l"(a), "l"(b));
}
__device__ __forceinline__ void mul2s(u64& c, u64 a) {
    asm("mul.rn.f32x2 %0, %0, %1;" : "+l"(c) : "l"(a));
}
__device__ __forceinline__ uint32_t smem_u32(const void* p) {
    uint32_t a;
    asm("{ .reg .u64 t; cvta.to.shared.u64 t, %1; cvt.u32.u64 %0, t; }"
        : "=r"(a) : "l"(p));
    return a;
}
__device__ __forceinline__ void ldsm4t(uint32_t* r, uint32_t a) {
    asm volatile("ldmatrix.sync.aligned.m8n8.x4.trans.shared.b16 {%0,%1,%2,%3}, [%4];"
                 : "=r"(r[0]), "=r"(r[1]), "=r"(r[2]), "=r"(r[3]) : "r"(a));
}
__device__ __forceinline__ void mma16816(float* c, const uint32_t* a, const uint32_t* b) {
    asm volatile(
        "mma.sync.aligned.m16n8k16.row.col.f32.bf16.bf16.f32 "
        "{%0,%1,%2,%3}, {%4,%5,%6,%7}, {%8,%9}, {%0,%1,%2,%3};"
        : "+f"(c[0]), "+f"(c[1]), "+f"(c[2]), "+f"(c[3])
        : "r"(a[0]), "r"(a[1]), "r"(a[2]), "r"(a[3]), "r"(b[0]), "r"(b[1]));
}

// ===================== prep: elementwise bf16 hi/lo split ===================
__device__ __forceinline__ uint32_t pack_bf2(float a, float b) {
    __nv_bfloat162 t = __floats2bfloat162_rn(a, b);
    return *reinterpret_cast<uint32_t*>(&t);
}
__device__ __forceinline__ void split4(const float4 v, uint32_t* oh, uint32_t* ol, int i) {
    __nv_bfloat16 h0 = __float2bfloat16(v.x), h1 = __float2bfloat16(v.y);
    __nv_bfloat16 h2 = __float2bfloat16(v.z), h3 = __float2bfloat16(v.w);
    oh[i * 2]     = pack_bf2(__bfloat162float(h0), __bfloat162float(h1));
    oh[i * 2 + 1] = pack_bf2(__bfloat162float(h2), __bfloat162float(h3));
    ol[i * 2]     = pack_bf2(v.x - __bfloat162float(h0), v.y - __bfloat162float(h1));
    ol[i * 2 + 1] = pack_bf2(v.z - __bfloat162float(h2), v.w - __bfloat162float(h3));
}
__global__ void prep_x_kernel(const float4* __restrict__ x) {
    int i = blockIdx.x * blockDim.x + threadIdx.x;   // over float4s
    split4(x[i], (uint32_t*)g_xh, (uint32_t*)g_xl, i);
}
__global__ void prep_w_kernel(const float4* __restrict__ w) {
    int i = blockIdx.x * blockDim.x + threadIdx.x;
    split4(w[i], (uint32_t*)g_wh, (uint32_t*)g_wl, i);
}

// ===================== Kernel 1: QKV GEMM via mma.sync (HMMA bf16) =========
// out[b, m, j] = sum_k x[b,k,m] * w[k,j] + bias[j], scattered to g_qkv.
// CTA: 128 m x 64 j, K-chunks of 64. 8 warps (4m x 2n), warp tile 32x32.
// 3-pass bf16 split: AhBh + AhBl + AlBh.
// smem layout (48 KB): AH[64][256B] 0, AL 16384, BH[64][128B] 32768, BL 40960.
#define QKV_SMEM 49152

__global__ void __launch_bounds__(256, 2) qkv_hmma_kernel(
    const float* __restrict__ bias)
{
    extern __shared__ char sm[];
    const int tid = threadIdx.x, lane = tid & 31, wid = tid >> 5;
    const int warp_m = wid & 3, warp_n = wid >> 2;
    const int j0 = blockIdx.x * 64, m0 = blockIdx.y * 128, b = blockIdx.z;

    float acc[2][4][4];
#pragma unroll
    for (int tm = 0; tm < 2; tm++)
#pragma unroll
        for (int tn = 0; tn < 4; tn++)
#pragma unroll
            for (int q = 0; q < 4; q++) acc[tm][tn][q] = 0.f;

    const uint32_t Ab = smem_u32(sm);
    const uint32_t Bb = Ab + 32768;
    const int g = lane >> 3, r8 = lane & 7;

    for (int ch = 0; ch < 8; ch++) {
        const int k0 = ch * 64;
        __syncthreads();
        // ---- copy: A-hi/lo 128x64 (as [k][m], 256 B rows), B-hi/lo 64x64 ----
        {
            const __nv_bfloat16* xh = g_xh + ((size_t)(b * CH + k0)) * NTOK + m0;
            const __nv_bfloat16* xl = g_xl + ((size_t)(b * CH + k0)) * NTOK + m0;
            const __nv_bfloat16* wh = g_wh + (size_t)k0 * TC + j0;
            const __nv_bfloat16* wl = g_wl + (size_t)k0 * TC + j0;
#pragma unroll
            for (int i = 0; i < 4; i++) {            // A-hi: 1024 16B chunks
                int q = tid + i * 256, k = q >> 4, c = q & 15;
                *(int4*)(sm + k * 256 + ((c ^ (k & 7)) << 4)) =
                    *(const int4*)(xh + k * NTOK + c * 8);
            }
#pragma unroll
            for (int i = 0; i < 4; i++) {            // A-lo
                int q = tid + i * 256, k = q >> 4, c = q & 15;
                *(int4*)(sm + 16384 + k * 256 + ((c ^ (k & 7)) << 4)) =
                    *(const int4*)(xl + k * NTOK + c * 8);
            }
#pragma unroll
            for (int i = 0; i < 2; i++) {            // B-hi: 512 chunks
                int q = tid + i * 256, k = q >> 3, c = q & 7;
                *(int4*)(sm + 32768 + k * 128 + ((c ^ (k & 7)) << 4)) =
                    *(const int4*)(wh + k * TC + c * 8);
            }
#pragma unroll
            for (int i = 0; i < 2; i++) {            // B-lo
                int q = tid + i * 256, k = q >> 3, c = q & 7;
                *(int4*)(sm + 40960 + k * 128 + ((c ^ (k & 7)) << 4)) =
                    *(const int4*)(wl + k * TC + c * 8);
            }
        }
        __syncthreads();

        // ---- compute 4 k-steps of 16 ----
#pragma unroll
        for (int ks = 0; ks < 4; ks++) {
            uint32_t ah[2][4], al[2][4], bh[2][4], bl[2][4];
            // A frags: groups g=0,1 -> k0-7 (cols c, c+1); g=2,3 -> k8-15
            const int klA = ks * 16 + ((g >> 1) << 3) + r8;
#pragma unroll
            for (int tm = 0; tm < 2; tm++) {
                int cc = ((warp_m * 32 + tm * 16) >> 3) + (g & 1);
                uint32_t off = klA * 256 + (((cc ^ (klA & 7))) << 4);
                ldsm4t(ah[tm], Ab + off);
                ldsm4t(al[tm], Ab + 16384 + off);
            }
            // B frags: groups g=0,1 -> k halves at col c; g=2,3 -> col c+1
            const int klB = ks * 16 + ((g & 1) << 3) + r8;
#pragma unroll
            for (int p = 0; p < 2; p++) {
                int cc = ((warp_n * 32 + p * 16) >> 3) + (g >> 1);
                uint32_t off = klB * 128 + (((cc ^ (klB & 7))) << 4);
                ldsm4t(bh[p], Bb + off);
                ldsm4t(bl[p], Bb + 8192 + off);
            }
#pragma unroll
            for (int tm = 0; tm < 2; tm++)
#pragma unroll
                for (int tn = 0; tn < 4; tn++) {
                    float* c = acc[tm][tn];
                    const uint32_t* bhp = &bh[tn >> 1][(tn & 1) * 2];
                    const uint32_t* blp = &bl[tn >> 1][(tn & 1) * 2];
                    mma16816(c, ah[tm], bhp);
                    mma16816(c, ah[tm], blp);
                    mma16816(c, al[tm], bhp);
                }
        }
    }

    // ---- epilogue: j0 is 64-aligned -> exactly one (s, h) per CTA ----
    const int s = j0 >> 9, h = (j0 >> 6) & (NH - 1);
    float* base = g_qkv + (((size_t)(s * BATCH + b) * NH + h) * NTOK + m0) * HD;
#pragma unroll
    for (int tn = 0; tn < 4; tn++) {
        const int d = warp_n * 32 + tn * 8 + 2 * (lane & 3);
        const float bv0 = bias[j0 + d], bv1 = bias[j0 + d + 1];
#pragma unroll
        for (int tm = 0; tm < 2; tm++) {
            const int row = warp_m * 32 + tm * 16 + (lane >> 2);
            float2 v0 = make_float2(acc[tm][tn][0] + bv0, acc[tm][tn][1] + bv1);
            float2 v1 = make_float2(acc[tm][tn][2] + bv0, acc[tm][tn][3] + bv1);
            *(float2*)(base + (size_t)row * HD + d) = v0;
            *(float2*)(base + (size_t)(row + 8) * HD + d) = v1;
        }
    }
}

// ---------------------------------------------------------------------------
// Kernel 2: Flash attention (unchanged from passing R2 version).
// ---------------------------------------------------------------------------
#define QS_STRIDE 68
#define VS_STRIDE 68
#define ATTN_SMEM ((128*QS_STRIDE + 64*128 + 128*VS_STRIDE + 128*128) * 4)

__global__ void __launch_bounds__(256, 1) attn_kernel()
{
    extern __shared__ float fsm[];
    float* Qs = fsm;
    float* Kt = Qs + 128 * QS_STRIDE;
    float* Vs = Kt + 64 * 128;
    float* Ps = Vs + 128 * VS_STRIDE;

    const int bh = blockIdx.x;
    const int m0 = blockIdx.y * 128;
    const int tid = threadIdx.x;
    const int tx = tid & 15, ty = tid >> 4;

    const float* qg = g_qkv + bh * (NTOK * HD);
    const float* kg = g_qkv + (BATCH * NH + bh) * (NTOK * HD);
    const float* vg = g_qkv + (2 * BATCH * NH + bh) * (NTOK * HD);

    {
        const int r  = tid >> 1;
        const int dh = (tid & 1) * 32;
        const float* src = qg + (m0 + r) * HD + dh;
#pragma unroll
        for (int q = 0; q < 8; q++) {
            float4 v = *(const float4*)(src + q * 4);
            v.x *= ATT_SCALE; v.y *= ATT_SCALE; v.z *= ATT_SCALE; v.w *= ATT_SCALE;
            *(float4*)&Qs[r * QS_STRIDE + dh + q * 4] = v;
        }
    }

    float mreg[8], lreg[8];
    u64 o2[8][2];
#pragma unroll
    for (int i = 0; i < 8; i++) {
        mreg[i] = -1e30f; lreg[i] = 0.f;
        o2[i][0] = 0ull; o2[i][1] = 0ull;
    }

    for (int n0 = 0; n0 < NTOK; n0 += 128) {
        __syncthreads();
        {
            const int jj = tid >> 1;
            const int dh = (tid & 1) * 32;
            const float* ks = kg + (n0 + jj) * HD + dh;
            const float* vs = vg + (n0 + jj) * HD + dh;
#pragma unroll
            for (int q = 0; q < 8; q++) {
                float4 kv = *(const float4*)(ks + q * 4);
                Kt[(dh + q * 4 + 0) * 128 + jj] = kv.x;
                Kt[(dh + q * 4 + 1) * 128 + jj] = kv.y;
                Kt[(dh + q * 4 + 2) * 128 + jj] = kv.z;
                Kt[(dh + q * 4 + 3) * 128 + jj] = kv.w;
                *(float4*)&Vs[jj * VS_STRIDE + dh + q * 4] = *(const float4*)(vs + q * 4);
            }
        }
        __syncthreads();

        u64 s2[8][4];
#pragma unroll
        for (int i = 0; i < 8; i++)
#pragma unroll
            for (int j = 0; j < 4; j++) s2[i][j] = 0ull;

        for (int d = 0; d < HD; d++) {
            ulonglong2 k0 = *(const ulonglong2*)&Kt[d * 128 + tx * 8];
            ulonglong2 k1 = *(const ulonglong2*)&Kt[d * 128 + tx * 8 + 4];
#pragma unroll
            for (int i = 0; i < 8; i++) {
                float qv = Qs[(ty * 8 + i) * QS_STRIDE + d];
                u64 qq = pk2(qv, qv);
                fma2(s2[i][0], qq, k0.x);
                fma2(s2[i][1], qq, k0.y);
                fma2(s2[i][2], qq, k1.x);
                fma2(s2[i][3], qq, k1.y);
            }
        }

#pragma unroll
        for (int i = 0; i < 8; i++) {
            float sv[8];
#pragma unroll
            for (int jp = 0; jp < 4; jp++) upk2(s2[i][jp], sv[jp * 2], sv[jp * 2 + 1]);
            float mx = sv[0];
#pragma unroll
            for (int jj = 1; jj < 8; jj++) mx = fmaxf(mx, sv[jj]);
#pragma unroll
            for (int sft = 8; sft > 0; sft >>= 1)
                mx = fmaxf(mx, __shfl_xor_sync(0xffffffffu, mx, sft));
            float newm  = fmaxf(mreg[i], mx);
            float alpha = __expf(mreg[i] - newm);
            mreg[i] = newm;
            float rs = 0.f;
            float e[8];
#pragma unroll
            for (int jj = 0; jj < 8; jj++) { e[jj] = __expf(sv[jj] - newm); rs += e[jj]; }
            *(float4*)&Ps[(ty * 8 + i) * 128 + tx * 8]     = make_float4(e[0], e[1], e[2], e[3]);
            *(float4*)&Ps[(ty * 8 + i) * 128 + tx * 8 + 4] = make_float4(e[4], e[5], e[6], e[7]);
#pragma unroll
            for (int sft = 8; sft > 0; sft >>= 1)
                rs += __shfl_xor_sync(0xffffffffu, rs, sft);
            lreg[i] = lreg[i] * alpha + rs;
            u64 ap = pk2(alpha, alpha);
            mul2s(o2[i][0], ap);
            mul2s(o2[i][1], ap);
        }
        __syncthreads();

        for (int j = 0; j < 128; j++) {
            ulonglong2 vv = *(const ulonglong2*)&Vs[j * VS_STRIDE + tx * 4];
#pragma unroll
            for (int i = 0; i < 8; i++) {
                float p = Ps[(ty * 8 + i) * 128 + j];
                u64 pp = pk2(p, p);
                fma2(o2[i][0], pp, vv.x);
                fma2(o2[i][1], pp, vv.y);
            }
        }
    }

    const int b = bh >> 3;
    const int h = bh & 7;
    float* outp = g_attn + (b * NTOK + m0) * CH + h * HD + tx * 4;
#pragma unroll
    for (int i = 0; i < 8; i++) {
        float inv = 1.0f / lreg[i];
        float f0, f1, f2, f3;
        upk2(o2[i][0], f0, f1);
        upk2(o2[i][1], f2, f3);
        *(float4*)(outp + (ty * 8 + i) * CH) =
            make_float4(f0 * inv, f1 * inv, f2 * inv, f3 * inv);
    }
}

// ---------------------------------------------------------------------------
// Kernel 3: Proj GEMM (unchanged from passing R2 version).
// ---------------------------------------------------------------------------
__global__ void __launch_bounds__(256, 1) proj_kernel(
    const float* __restrict__ w, const float* __restrict__ bias,
    float* __restrict__ out)
{
    __shared__ u64   As2[16][128];
    __shared__ float Bs[16][128];

    const int b  = blockIdx.z;
    const int m0 = blockIdx.y * 128;
    const int j0 = blockIdx.x * 128;
    const int tid = threadIdx.x;
    const int tx = tid & 15, ty = tid >> 4;

    const float* A = g_attn + b * NTOK * CH;

    u64 acc[8][4];
#pragma unroll
    for (int i = 0; i < 8; i++)
#pragma unroll
        for (int j = 0; j < 4; j++) acc[i][j] = 0ull;

    const int lm  = tid >> 1;
    const int lkh = (tid & 1) * 8;
    const int lk = tid >> 4, lj = (tid & 15) * 8;

    for (int k0 = 0; k0 < CH; k0 += 16) {
        const float* ap = A + (m0 + lm) * CH + k0 + lkh;
        float4 a0 = *(const float4*)ap;
        float4 a1 = *(const float4*)(ap + 4);
        As2[lkh + 0][lm] = pk2(a0.x, a0.x);
        As2[lkh + 1][lm] = pk2(a0.y, a0.y);
        As2[lkh + 2][lm] = pk2(a0.z, a0.z);
        As2[lkh + 3][lm] = pk2(a0.w, a0.w);
        As2[lkh + 4][lm] = pk2(a1.x, a1.x);
        As2[lkh + 5][lm] = pk2(a1.y, a1.y);
        As2[lkh + 6][lm] = pk2(a1.z, a1.z);
        As2[lkh + 7][lm] = pk2(a1.w, a1.w);
        const float* bp = w + (k0 + lk) * CH + j0 + lj;
        *(float4*)&Bs[lk][lj]     = *(const float4*)bp;
        *(float4*)&Bs[lk][lj + 4] = *(const float4*)(bp + 4);
        __syncthreads();
#pragma unroll
        for (int kk = 0; kk < 16; kk++) {
            u64 a[8];
#pragma unroll
            for (int i = 0; i < 8; i++) a[i] = As2[kk][ty * 8 + i];
            ulonglong2 b0 = *(const ulonglong2*)&Bs[kk][tx * 8];
            ulonglong2 b1 = *(const ulonglong2*)&Bs[kk][tx * 8 + 4];
            u64 bp4[4] = { b0.x, b0.y, b1.x, b1.y };
#pragma unroll
            for (int i = 0; i < 8; i++)
#pragma unroll
                for (int j = 0; j < 4; j++) fma2(acc[i][j], a[i], bp4[j]);
        }
        __syncthreads();
    }

    float4 bv0 = *(const float4*)(bias + j0 + tx * 8);
    float4 bv1 = *(const float4*)(bias + j0 + tx * 8 + 4);
    float bb[8] = { bv0.x, bv0.y, bv0.z, bv0.w, bv1.x, bv1.y, bv1.z, bv1.w };
    float f[8][8];
#pragma unroll
    for (int i = 0; i < 8; i++)
#pragma unroll
        for (int jp = 0; jp < 4; jp++) upk2(acc[i][jp], f[i][jp * 2], f[i][jp * 2 + 1]);
    float* ob = out + b * CH * NTOK + (j0 + tx * 8) * NTOK + m0 + ty * 8;
#pragma unroll
    for (int jj = 0; jj < 8; jj++) {
        *(float4*)(ob + jj * NTOK) =
            make_float4(f[0][jj] + bb[jj], f[1][jj] + bb[jj],
                        f[2][jj] + bb[jj], f[3][jj] + bb[jj]);
        *(float4*)(ob + jj * NTOK + 4) =
            make_float4(f[4][jj] + bb[jj], f[5][jj] + bb[jj],
                        f[6][jj] + bb[jj], f[7][jj] + bb[jj]);
    }
}

// ---------------------------------------------------------------------------
extern "C" void kernel_launch(void* const* d_in, const int* in_sizes, int n_in,
                              void* d_out, int out_size)
{
    const float* x      = (const float*)d_in[0];
    const float* w_qkv  = (const float*)d_in[1];
    const float* b_qkv  = (const float*)d_in[2];
    const float* w_proj = (const float*)d_in[3];
    const float* b_proj = (const float*)d_in[4];
    float* out = (float*)d_out;

    cudaFuncSetAttribute(attn_kernel,
                         cudaFuncAttributeMaxDynamicSharedMemorySize, ATTN_SMEM);
    cudaFuncSetAttribute(qkv_hmma_kernel,
                         cudaFuncAttributeMaxDynamicSharedMemorySize, QKV_SMEM);

    prep_x_kernel<<<(BATCH * CH * NTOK / 4) / 256, 256>>>((const float4*)x);
    prep_w_kernel<<<(CH * TC / 4) / 256, 256>>>((const float4*)w_qkv);
    qkv_hmma_kernel<<<dim3(TC / 64, NTOK / 128, BATCH), 256, QKV_SMEM>>>(b_qkv);
    attn_kernel<<<dim3(BATCH * NH, NTOK / 128), 256, ATTN_SMEM>>>();
    proj_kernel<<<dim3(CH / 128, NTOK / 128, BATCH), 256>>>(w_proj, b_proj, out);
}

// round 8
// speedup vs baseline: 2.2254x; 1.6841x over previous
#include <cuda_runtime.h>
#include <cuda_bf16.h>
#include <cstdint>

#define BATCH 8
#define CH    512
#define NTOK  1024
#define NH    8
#define HD    64
#define TC    1536
#define ATT_SCALE 0.125f

// Scratch (allocation-free rule: __device__ globals)
__device__ float g_attn[BATCH * NTOK * CH];           // [b][n][c]

// bf16 hi/lo split inputs for QKV GEMM (original layouts)
__device__ __align__(16) __nv_bfloat16 g_xh[BATCH * CH * NTOK];  // [b][k][m]
__device__ __align__(16) __nv_bfloat16 g_xl[BATCH * CH * NTOK];
__device__ __align__(16) __nv_bfloat16 g_wh[CH * TC];            // [k][j]
__device__ __align__(16) __nv_bfloat16 g_wl[CH * TC];

// attention operands, written by QKV epilogue
__device__ __align__(16) __nv_bfloat16 g_qh[BATCH * NH * HD * NTOK]; // [b][h][d][n], pre-scaled
__device__ __align__(16) __nv_bfloat16 g_ql[BATCH * NH * HD * NTOK];
__device__ __align__(16) __nv_bfloat16 g_kh[BATCH * NH * HD * NTOK]; // [b][h][d][n]
__device__ __align__(16) __nv_bfloat16 g_kl[BATCH * NH * HD * NTOK];
__device__ __align__(16) __nv_bfloat16 g_vh[BATCH * NH * NTOK * HD]; // [b][h][n][d]
__device__ __align__(16) __nv_bfloat16 g_vl[BATCH * NH * NTOK * HD];

typedef unsigned long long u64;

__device__ __forceinline__ u64 pk2(float lo, float hi) {
    u64 r; asm("mov.b64 %0, {%1,%2};" : "=l"(r) : "f"(lo), "f"(hi)); return r;
}
__device__ __forceinline__ void upk2(u64 v, float& lo, float& hi) {
    asm("mov.b64 {%0,%1}, %2;" : "=f"(lo), "=f"(hi) : "l"(v));
}
__device__ __forceinline__ void fma2(u64& c, u64 a, u64 b) {
    asm("fma.rn.f32x2 %0, %1, %2, %0;" : "+l"(c) : "l"(a), "l"(b));
}
__device__ __forceinline__ uint32_t smem_u32(const void* p) {
    uint32_t a;
    asm("{ .reg .u64 t; cvta.to.shared.u64 t, %1; cvt.u32.u64 %0, t; }"
        : "=r"(a) : "l"(p));
    return a;
}
__device__ __forceinline__ void ldsm4t(uint32_t* r, uint32_t a) {
    asm volatile("ldmatrix.sync.aligned.m8n8.x4.trans.shared.b16 {%0,%1,%2,%3}, [%4];"
                 : "=r"(r[0]), "=r"(r[1]), "=r"(r[2]), "=r"(r[3]) : "r"(a));
}
__device__ __forceinline__ void mma16816(float* c, const uint32_t* a, const uint32_t* b) {
    asm volatile(
        "mma.sync.aligned.m16n8k16.row.col.f32.bf16.bf16.f32 "
        "{%0,%1,%2,%3}, {%4,%5,%6,%7}, {%8,%9}, {%0,%1,%2,%3};"
        : "+f"(c[0]), "+f"(c[1]), "+f"(c[2]), "+f"(c[3])
        : "r"(a[0]), "r"(a[1]), "r"(a[2]), "r"(a[3]), "r"(b[0]), "r"(b[1]));
}
__device__ __forceinline__ uint32_t pack_bf2(float a, float b) {
    __nv_bfloat162 t = __floats2bfloat162_rn(a, b);
    return *reinterpret_cast<uint32_t*>(&t);
}
__device__ __forceinline__ uint32_t pack_bb(__nv_bfloat16 a, __nv_bfloat16 b) {
    __nv_bfloat162 t(a, b);
    return *reinterpret_cast<uint32_t*>(&t);
}
// pack pair to bf16 hi, and residual lo
__device__ __forceinline__ uint32_t split_pair(float f0, float f1, uint32_t& lo) {
    __nv_bfloat16 h0 = __float2bfloat16(f0), h1 = __float2bfloat16(f1);
    lo = pack_bf2(f0 - __bfloat162float(h0), f1 - __bfloat162float(h1));
    return pack_bb(h0, h1);
}

// ===================== prep: elementwise bf16 hi/lo split ===================
__device__ __forceinline__ void split4(const float4 v, uint32_t* oh, uint32_t* ol, int i) {
    __nv_bfloat16 h0 = __float2bfloat16(v.x), h1 = __float2bfloat16(v.y);
    __nv_bfloat16 h2 = __float2bfloat16(v.z), h3 = __float2bfloat16(v.w);
    oh[i * 2]     = pack_bb(h0, h1);
    oh[i * 2 + 1] = pack_bb(h2, h3);
    ol[i * 2]     = pack_bf2(v.x - __bfloat162float(h0), v.y - __bfloat162float(h1));
    ol[i * 2 + 1] = pack_bf2(v.z - __bfloat162float(h2), v.w - __bfloat162float(h3));
}
__global__ void prep_x_kernel(const float4* __restrict__ x) {
    int i = blockIdx.x * blockDim.x + threadIdx.x;
    split4(x[i], (uint32_t*)g_xh, (uint32_t*)g_xl, i);
}
__global__ void prep_w_kernel(const float4* __restrict__ w) {
    int i = blockIdx.x * blockDim.x + threadIdx.x;
    split4(w[i], (uint32_t*)g_wh, (uint32_t*)g_wl, i);
}

// ===================== Kernel 1: QKV GEMM via mma.sync (HMMA bf16) =========
// out[b, m, j] = sum_k x[b,k,m] * w[k,j] + bias[j].
// Epilogue writes bf16 hi/lo attention operands:
//   s=0 Q (scaled): [b][h][d][n]   s=1 K: [b][h][d][n]   s=2 V: [b][h][n][d]
#define QKV_SMEM 49152

__global__ void __launch_bounds__(256, 2) qkv_hmma_kernel(
    const float* __restrict__ bias)
{
    extern __shared__ char sm[];
    const int tid = threadIdx.x, lane = tid & 31, wid = tid >> 5;
    const int warp_m = wid & 3, warp_n = wid >> 2;
    const int j0 = blockIdx.x * 64, m0 = blockIdx.y * 128, b = blockIdx.z;

    float acc[2][4][4];
#pragma unroll
    for (int tm = 0; tm < 2; tm++)
#pragma unroll
        for (int tn = 0; tn < 4; tn++)
#pragma unroll
            for (int q = 0; q < 4; q++) acc[tm][tn][q] = 0.f;

    const uint32_t Ab = smem_u32(sm);
    const uint32_t Bb = Ab + 32768;
    const int g = lane >> 3, r8 = lane & 7;

    for (int ch = 0; ch < 8; ch++) {
        const int k0 = ch * 64;
        __syncthreads();
        {
            const __nv_bfloat16* xh = g_xh + ((size_t)(b * CH + k0)) * NTOK + m0;
            const __nv_bfloat16* xl = g_xl + ((size_t)(b * CH + k0)) * NTOK + m0;
            const __nv_bfloat16* wh = g_wh + (size_t)k0 * TC + j0;
            const __nv_bfloat16* wl = g_wl + (size_t)k0 * TC + j0;
#pragma unroll
            for (int i = 0; i < 4; i++) {
                int q = tid + i * 256, k = q >> 4, c = q & 15;
                *(int4*)(sm + k * 256 + ((c ^ (k & 7)) << 4)) =
                    *(const int4*)(xh + k * NTOK + c * 8);
            }
#pragma unroll
            for (int i = 0; i < 4; i++) {
                int q = tid + i * 256, k = q >> 4, c = q & 15;
                *(int4*)(sm + 16384 + k * 256 + ((c ^ (k & 7)) << 4)) =
                    *(const int4*)(xl + k * NTOK + c * 8);
            }
#pragma unroll
            for (int i = 0; i < 2; i++) {
                int q = tid + i * 256, k = q >> 3, c = q & 7;
                *(int4*)(sm + 32768 + k * 128 + ((c ^ (k & 7)) << 4)) =
                    *(const int4*)(wh + k * TC + c * 8);
            }
#pragma unroll
            for (int i = 0; i < 2; i++) {
                int q = tid + i * 256, k = q >> 3, c = q & 7;
                *(int4*)(sm + 40960 + k * 128 + ((c ^ (k & 7)) << 4)) =
                    *(const int4*)(wl + k * TC + c * 8);
            }
        }
        __syncthreads();

#pragma unroll
        for (int ks = 0; ks < 4; ks++) {
            uint32_t ah[2][4], al[2][4], bh[2][4], bl[2][4];
            const int klA = ks * 16 + ((g >> 1) << 3) + r8;
#pragma unroll
            for (int tm = 0; tm < 2; tm++) {
                int cc = ((warp_m * 32 + tm * 16) >> 3) + (g & 1);
                uint32_t off = klA * 256 + (((cc ^ (klA & 7))) << 4);
                ldsm4t(ah[tm], Ab + off);
                ldsm4t(al[tm], Ab + 16384 + off);
            }
            const int klB = ks * 16 + ((g & 1) << 3) + r8;
#pragma unroll
            for (int p = 0; p < 2; p++) {
                int cc = ((warp_n * 32 + p * 16) >> 3) + (g >> 1);
                uint32_t off = klB * 128 + (((cc ^ (klB & 7))) << 4);
                ldsm4t(bh[p], Bb + off);
                ldsm4t(bl[p], Bb + 8192 + off);
            }
#pragma unroll
            for (int tm = 0; tm < 2; tm++)
#pragma unroll
                for (int tn = 0; tn < 4; tn++) {
                    float* c = acc[tm][tn];
                    const uint32_t* bhp = &bh[tn >> 1][(tn & 1) * 2];
                    const uint32_t* blp = &bl[tn >> 1][(tn & 1) * 2];
                    mma16816(c, ah[tm], bhp);
                    mma16816(c, ah[tm], blp);
                    mma16816(c, al[tm], bhp);
                }
        }
    }

    // ---- epilogue: j0 64-aligned -> one (s, h) per CTA; split to bf16 ----
    const int s = j0 >> 9;
    const int h = (j0 >> 6) & (NH - 1);
    const int bhh = b * NH + h;
#pragma unroll
    for (int tn = 0; tn < 4; tn++) {
        const int d = warp_n * 32 + tn * 8 + 2 * (lane & 3);
        const float bv0 = bias[j0 + d], bv1 = bias[j0 + d + 1];
#pragma unroll
        for (int tm = 0; tm < 2; tm++) {
            const int n = m0 + warp_m * 32 + tm * 16 + (lane >> 2);
            float v0 = acc[tm][tn][0] + bv0, v1 = acc[tm][tn][1] + bv1;
            float v2 = acc[tm][tn][2] + bv0, v3 = acc[tm][tn][3] + bv1;
            if (s == 2) {
                uint32_t lo, hi;
                size_t a0 = ((size_t)bhh * NTOK + n) * HD + d;
                hi = split_pair(v0, v1, lo);
                *(uint32_t*)&g_vh[a0] = hi; *(uint32_t*)&g_vl[a0] = lo;
                size_t a1 = a0 + 8 * HD;
                hi = split_pair(v2, v3, lo);
                *(uint32_t*)&g_vh[a1] = hi; *(uint32_t*)&g_vl[a1] = lo;
            } else {
                if (s == 0) { v0 *= ATT_SCALE; v1 *= ATT_SCALE; v2 *= ATT_SCALE; v3 *= ATT_SCALE; }
                __nv_bfloat16* dh = (s == 0) ? g_qh : g_kh;
                __nv_bfloat16* dl = (s == 0) ? g_ql : g_kl;
                const size_t b0 = ((size_t)bhh * HD + d) * NTOK;
                const size_t b1 = b0 + NTOK;
                __nv_bfloat16 t;
                t = __float2bfloat16(v0); dh[b0 + n] = t; dl[b0 + n] = __float2bfloat16(v0 - __bfloat162float(t));
                t = __float2bfloat16(v1); dh[b1 + n] = t; dl[b1 + n] = __float2bfloat16(v1 - __bfloat162float(t));
                t = __float2bfloat16(v2); dh[b0 + n + 8] = t; dl[b0 + n + 8] = __float2bfloat16(v2 - __bfloat162float(t));
                t = __float2bfloat16(v3); dh[b1 + n + 8] = t; dl[b1 + n + 8] = __float2bfloat16(v3 - __bfloat162float(t));
            }
        }
    }
}

// ===================== Kernel 2: Flash attention via HMMA ===================
// CTA: (bh, 128-row Q block). 8 warps; warp w owns rows w*16..w*16+15.
// smem: Qh/Ql [64][256B], Kh/Kl [64][256B], Vh/Vl [128][128B]  = 96 KB.
#define ATTN_SMEM (96 * 1024)

__global__ void __launch_bounds__(256) attn_hmma_kernel()
{
    extern __shared__ char sm[];
    const uint32_t Qh = smem_u32(sm);
    const uint32_t Ql = Qh + 16384;
    const uint32_t Kh = Qh + 32768;
    const uint32_t Kl = Qh + 49152;
    const uint32_t Vh = Qh + 65536;
    const uint32_t Vl = Qh + 81920;

    const int tid = threadIdx.x, lane = tid & 31, w = tid >> 5;
    const int g = lane >> 3, r8 = lane & 7;
    const int bh = blockIdx.x;             // b*NH + h
    const int m0 = blockIdx.y * 128;

    const __nv_bfloat16* qh = g_qh + (size_t)bh * HD * NTOK;   // [d][n]
    const __nv_bfloat16* ql = g_ql + (size_t)bh * HD * NTOK;
    const __nv_bfloat16* kh = g_kh + (size_t)bh * HD * NTOK;   // [d][n]
    const __nv_bfloat16* kl = g_kl + (size_t)bh * HD * NTOK;
    const __nv_bfloat16* vh = g_vh + (size_t)bh * NTOK * HD;   // [n][d]
    const __nv_bfloat16* vl = g_vl + (size_t)bh * NTOK * HD;

    // ---- load Q tile (once): [d=64][qrow=128] 256B rows ----
#pragma unroll
    for (int i = 0; i < 4; i++) {
        int q = tid + i * 256, k = q >> 4, c = q & 15;
        uint32_t off = k * 256 + ((c ^ (k & 7)) << 4);
        *(int4*)(sm + off)         = *(const int4*)(qh + (size_t)k * NTOK + m0 + c * 8);
        *(int4*)(sm + 16384 + off) = *(const int4*)(ql + (size_t)k * NTOK + m0 + c * 8);
    }
    __syncthreads();

    // ---- preload Q A-fragments (persistent) ----
    uint32_t aqh[4][4], aql[4][4];
    {
        const int ccA = 2 * w + (g & 1);
#pragma unroll
        for (int ks = 0; ks < 4; ks++) {
            const int klA = ks * 16 + ((g >> 1) << 3) + r8;
            uint32_t off = klA * 256 + ((ccA ^ (klA & 7)) << 4);
            ldsm4t(aqh[ks], Qh + off);
            ldsm4t(aql[ks], Ql + off);
        }
    }

    float mr0 = -1e30f, mr1 = -1e30f, l0 = 0.f, l1 = 0.f;
    float of[8][4];
#pragma unroll
    for (int tn = 0; tn < 8; tn++)
#pragma unroll
        for (int q = 0; q < 4; q++) of[tn][q] = 0.f;

    for (int nb = 0; nb < 8; nb++) {
        const int n0 = nb * 128;
        __syncthreads();
        // ---- load K tile [d=64][key=128] and V tile [key=128][d=64] ----
#pragma unroll
        for (int i = 0; i < 4; i++) {
            int q = tid + i * 256, k = q >> 4, c = q & 15;
            uint32_t off = k * 256 + ((c ^ (k & 7)) << 4);
            *(int4*)(sm + 32768 + off) = *(const int4*)(kh + (size_t)k * NTOK + n0 + c * 8);
            *(int4*)(sm + 49152 + off) = *(const int4*)(kl + (size_t)k * NTOK + n0 + c * 8);
        }
#pragma unroll
        for (int i = 0; i < 4; i++) {
            int q = tid + i * 256, k = q >> 3, c = q & 7;
            uint32_t off = k * 128 + ((c ^ (k & 7)) << 4);
            *(int4*)(sm + 65536 + off) = *(const int4*)(vh + (size_t)(n0 + k) * HD + c * 8);
            *(int4*)(sm + 81920 + off) = *(const int4*)(vl + (size_t)(n0 + k) * HD + c * 8);
        }
        __syncthreads();

        // ---- S = Q K^T : 16 rows x 128 keys per warp, split-3 ----
        float sf[16][4];
#pragma unroll
        for (int t = 0; t < 16; t++)
#pragma unroll
            for (int q = 0; q < 4; q++) sf[t][q] = 0.f;

#pragma unroll
        for (int ks = 0; ks < 4; ks++) {
            const int klB = ks * 16 + ((g & 1) << 3) + r8;
#pragma unroll
            for (int tp = 0; tp < 8; tp++) {
                uint32_t bk[4], bkl[4];
                const int cc = tp * 2 + (g >> 1);
                uint32_t off = klB * 256 + ((cc ^ (klB & 7)) << 4);
                ldsm4t(bk, Kh + off);
                ldsm4t(bkl, Kl + off);
                mma16816(sf[2 * tp],     aqh[ks], &bk[0]);
                mma16816(sf[2 * tp],     aqh[ks], &bkl[0]);
                mma16816(sf[2 * tp],     aql[ks], &bk[0]);
                mma16816(sf[2 * tp + 1], aqh[ks], &bk[2]);
                mma16816(sf[2 * tp + 1], aqh[ks], &bkl[2]);
                mma16816(sf[2 * tp + 1], aql[ks], &bk[2]);
            }
        }

        // ---- online softmax (rows r = w*16 + lane/4 and r+8) ----
        float mx0 = -1e30f, mx1 = -1e30f;
#pragma unroll
        for (int t = 0; t < 16; t++) {
            mx0 = fmaxf(mx0, fmaxf(sf[t][0], sf[t][1]));
            mx1 = fmaxf(mx1, fmaxf(sf[t][2], sf[t][3]));
        }
        mx0 = fmaxf(mx0, __shfl_xor_sync(0xffffffffu, mx0, 1));
        mx0 = fmaxf(mx0, __shfl_xor_sync(0xffffffffu, mx0, 2));
        mx1 = fmaxf(mx1, __shfl_xor_sync(0xffffffffu, mx1, 1));
        mx1 = fmaxf(mx1, __shfl_xor_sync(0xffffffffu, mx1, 2));
        const float nm0 = fmaxf(mr0, mx0), nm1 = fmaxf(mr1, mx1);
        const float a0 = __expf(mr0 - nm0), a1 = __expf(mr1 - nm1);
        mr0 = nm0; mr1 = nm1;
        float rs0 = 0.f, rs1 = 0.f;
#pragma unroll
        for (int t = 0; t < 16; t++) {
            sf[t][0] = __expf(sf[t][0] - nm0);
            sf[t][1] = __expf(sf[t][1] - nm0);
            sf[t][2] = __expf(sf[t][2] - nm1);
            sf[t][3] = __expf(sf[t][3] - nm1);
            rs0 += sf[t][0] + sf[t][1];
            rs1 += sf[t][2] + sf[t][3];
        }
        rs0 += __shfl_xor_sync(0xffffffffu, rs0, 1);
        rs0 += __shfl_xor_sync(0xffffffffu, rs0, 2);
        rs1 += __shfl_xor_sync(0xffffffffu, rs1, 1);
        rs1 += __shfl_xor_sync(0xffffffffu, rs1, 2);
        l0 = l0 * a0 + rs0;
        l1 = l1 * a1 + rs1;
#pragma unroll
        for (int tn = 0; tn < 8; tn++) {
            of[tn][0] *= a0; of[tn][1] *= a0;
            of[tn][2] *= a1; of[tn][3] *= a1;
        }

        // ---- O += P V : P built in registers from S fragments ----
#pragma unroll
        for (int ks = 0; ks < 8; ks++) {
            uint32_t pah[4], pal[4];
            pah[0] = split_pair(sf[2 * ks][0],     sf[2 * ks][1],     pal[0]);
            pah[1] = split_pair(sf[2 * ks][2],     sf[2 * ks][3],     pal[1]);
            pah[2] = split_pair(sf[2 * ks + 1][0], sf[2 * ks + 1][1], pal[2]);
            pah[3] = split_pair(sf[2 * ks + 1][2], sf[2 * ks + 1][3], pal[3]);
            const int klV = ks * 16 + ((g & 1) << 3) + r8;
#pragma unroll
            for (int tp = 0; tp < 4; tp++) {
                uint32_t bv[4], bvl[4];
                const int cc = tp * 2 + (g >> 1);
                uint32_t off = klV * 128 + ((cc ^ (klV & 7)) << 4);
                ldsm4t(bv, Vh + off);
                ldsm4t(bvl, Vl + off);
                mma16816(of[2 * tp],     pah, &bv[0]);
                mma16816(of[2 * tp],     pah, &bvl[0]);
                mma16816(of[2 * tp],     pal, &bv[0]);
                mma16816(of[2 * tp + 1], pah, &bv[2]);
                mma16816(of[2 * tp + 1], pah, &bvl[2]);
                mma16816(of[2 * tp + 1], pal, &bv[2]);
            }
        }
    }

    // ---- normalize + write O to g_attn[b][n][h*64+d] ----
    const int b = bh >> 3, h = bh & 7;
    const float inv0 = 1.f / l0, inv1 = 1.f / l1;
    const int r = w * 16 + (lane >> 2);
    float* ob = g_attn + ((size_t)b * NTOK + m0) * CH + h * HD;
#pragma unroll
    for (int tn = 0; tn < 8; tn++) {
        const int d = tn * 8 + 2 * (lane & 3);
        *(float2*)(ob + (size_t)r * CH + d) =
            make_float2(of[tn][0] * inv0, of[tn][1] * inv0);
        *(float2*)(ob + (size_t)(r + 8) * CH + d) =
            make_float2(of[tn][2] * inv1, of[tn][3] * inv1);
    }
}

// ---------------------------------------------------------------------------
// Kernel 3: Proj GEMM (unchanged FFMA2 version).
// ---------------------------------------------------------------------------
__global__ void __launch_bounds__(256, 1) proj_kernel(
    const float* __restrict__ w, const float* __restrict__ bias,
    float* __restrict__ out)
{
    __shared__ u64   As2[16][128];
    __shared__ float Bs[16][128];

    const int b  = blockIdx.z;
    const int m0 = blockIdx.y * 128;
    const int j0 = blockIdx.x * 128;
    const int tid = threadIdx.x;
    const int tx = tid & 15, ty = tid >> 4;

    const float* A = g_attn + b * NTOK * CH;

    u64 acc[8][4];
#pragma unroll
    for (int i = 0; i < 8; i++)
#pragma unroll
        for (int j = 0; j < 4; j++) acc[i][j] = 0ull;

    const int lm  = tid >> 1;
    const int lkh = (tid & 1) * 8;
    const int lk = tid >> 4, lj = (tid & 15) * 8;

    for (int k0 = 0; k0 < CH; k0 += 16) {
        const float* ap = A + (m0 + lm) * CH + k0 + lkh;
        float4 a0 = *(const float4*)ap;
        float4 a1 = *(const float4*)(ap + 4);
        As2[lkh + 0][lm] = pk2(a0.x, a0.x);
        As2[lkh + 1][lm] = pk2(a0.y, a0.y);
        As2[lkh + 2][lm] = pk2(a0.z, a0.z);
        As2[lkh + 3][lm] = pk2(a0.w, a0.w);
        As2[lkh + 4][lm] = pk2(a1.x, a1.x);
        As2[lkh + 5][lm] = pk2(a1.y, a1.y);
        As2[lkh + 6][lm] = pk2(a1.z, a1.z);
        As2[lkh + 7][lm] = pk2(a1.w, a1.w);
        const float* bp = w + (k0 + lk) * CH + j0 + lj;
        *(float4*)&Bs[lk][lj]     = *(const float4*)bp;
        *(float4*)&Bs[lk][lj + 4] = *(const float4*)(bp + 4);
        __syncthreads();
#pragma unroll
        for (int kk = 0; kk < 16; kk++) {
            u64 a[8];
#pragma unroll
            for (int i = 0; i < 8; i++) a[i] = As2[kk][ty * 8 + i];
            ulonglong2 b0 = *(const ulonglong2*)&Bs[kk][tx * 8];
            ulonglong2 b1 = *(const ulonglong2*)&Bs[kk][tx * 8 + 4];
            u64 bp4[4] = { b0.x, b0.y, b1.x, b1.y };
#pragma unroll
            for (int i = 0; i < 8; i++)
#pragma unroll
                for (int j = 0; j < 4; j++) fma2(acc[i][j], a[i], bp4[j]);
        }
        __syncthreads();
    }

    float4 bv0 = *(const float4*)(bias + j0 + tx * 8);
    float4 bv1 = *(const float4*)(bias + j0 + tx * 8 + 4);
    float bb[8] = { bv0.x, bv0.y, bv0.z, bv0.w, bv1.x, bv1.y, bv1.z, bv1.w };
    float f[8][8];
#pragma unroll
    for (int i = 0; i < 8; i++)
#pragma unroll
        for (int jp = 0; jp < 4; jp++) upk2(acc[i][jp], f[i][jp * 2], f[i][jp * 2 + 1]);
    float* ob = out + b * CH * NTOK + (j0 + tx * 8) * NTOK + m0 + ty * 8;
#pragma unroll
    for (int jj = 0; jj < 8; jj++) {
        *(float4*)(ob + jj * NTOK) =
            make_float4(f[0][jj] + bb[jj], f[1][jj] + bb[jj],
                        f[2][jj] + bb[jj], f[3][jj] + bb[jj]);
        *(float4*)(ob + jj * NTOK + 4) =
            make_float4(f[4][jj] + bb[jj], f[5][jj] + bb[jj],
                        f[6][jj] + bb[jj], f[7][jj] + bb[jj]);
    }
}

// ---------------------------------------------------------------------------
extern "C" void kernel_launch(void* const* d_in, const int* in_sizes, int n_in,
                              void* d_out, int out_size)
{
    const float* x      = (const float*)d_in[0];
    const float* w_qkv  = (const float*)d_in[1];
    const float* b_qkv  = (const float*)d_in[2];
    const float* w_proj = (const float*)d_in[3];
    const float* b_proj = (const float*)d_in[4];
    float* out = (float*)d_out;

    cudaFuncSetAttribute(qkv_hmma_kernel,
                         cudaFuncAttributeMaxDynamicSharedMemorySize, QKV_SMEM);
    cudaFuncSetAttribute(attn_hmma_kernel,
                         cudaFuncAttributeMaxDynamicSharedMemorySize, ATTN_SMEM);

    prep_x_kernel<<<(BATCH * CH * NTOK / 4) / 256, 256>>>((const float4*)x);
    prep_w_kernel<<<(CH * TC / 4) / 256, 256>>>((const float4*)w_qkv);
    qkv_hmma_kernel<<<dim3(TC / 64, NTOK / 128, BATCH), 256, QKV_SMEM>>>(b_qkv);
    attn_hmma_kernel<<<dim3(BATCH * NH, NTOK / 128), 256, ATTN_SMEM>>>();
    proj_kernel<<<dim3(CH / 128, NTOK / 128, BATCH), 256>>>(w_proj, b_proj, out);
}

// round 9
// speedup vs baseline: 2.7845x; 1.2513x over previous
#include <cuda_runtime.h>
#include <cuda_bf16.h>
#include <cstdint>

#define BATCH 8
#define CH    512
#define NTOK  1024
#define NH    8
#define HD    64
#define TC    1536
#define ATT_SCALE 0.125f

// bf16 hi/lo split inputs for QKV GEMM (original layouts)
__device__ __align__(16) __nv_bfloat16 g_xh[BATCH * CH * NTOK];  // [b][k][m]
__device__ __align__(16) __nv_bfloat16 g_xl[BATCH * CH * NTOK];
__device__ __align__(16) __nv_bfloat16 g_wh[CH * TC];            // [k][j]
__device__ __align__(16) __nv_bfloat16 g_wl[CH * TC];
// w_proj hi/lo
__device__ __align__(16) __nv_bfloat16 g_pwh[CH * CH];           // [c][j]
__device__ __align__(16) __nv_bfloat16 g_pwl[CH * CH];

// attention operands, written by QKV epilogue
__device__ __align__(16) __nv_bfloat16 g_qh[BATCH * NH * HD * NTOK]; // [b][h][d][n], pre-scaled
__device__ __align__(16) __nv_bfloat16 g_ql[BATCH * NH * HD * NTOK];
__device__ __align__(16) __nv_bfloat16 g_kh[BATCH * NH * HD * NTOK]; // [b][h][d][n]
__device__ __align__(16) __nv_bfloat16 g_kl[BATCH * NH * HD * NTOK];
__device__ __align__(16) __nv_bfloat16 g_vh[BATCH * NH * NTOK * HD]; // [b][h][n][d]
__device__ __align__(16) __nv_bfloat16 g_vl[BATCH * NH * NTOK * HD];
// attention output, transposed, bf16 hi/lo: [b][c][n]
__device__ __align__(16) __nv_bfloat16 g_oh[BATCH * CH * NTOK];
__device__ __align__(16) __nv_bfloat16 g_ol[BATCH * CH * NTOK];

__device__ __forceinline__ uint32_t smem_u32(const void* p) {
    uint32_t a;
    asm("{ .reg .u64 t; cvta.to.shared.u64 t, %1; cvt.u32.u64 %0, t; }"
        : "=r"(a) : "l"(p));
    return a;
}
__device__ __forceinline__ void ldsm4t(uint32_t* r, uint32_t a) {
    asm volatile("ldmatrix.sync.aligned.m8n8.x4.trans.shared.b16 {%0,%1,%2,%3}, [%4];"
                 : "=r"(r[0]), "=r"(r[1]), "=r"(r[2]), "=r"(r[3]) : "r"(a));
}
__device__ __forceinline__ void mma16816(float* c, const uint32_t* a, const uint32_t* b) {
    asm volatile(
        "mma.sync.aligned.m16n8k16.row.col.f32.bf16.bf16.f32 "
        "{%0,%1,%2,%3}, {%4,%5,%6,%7}, {%8,%9}, {%0,%1,%2,%3};"
        : "+f"(c[0]), "+f"(c[1]), "+f"(c[2]), "+f"(c[3])
        : "r"(a[0]), "r"(a[1]), "r"(a[2]), "r"(a[3]), "r"(b[0]), "r"(b[1]));
}
__device__ __forceinline__ uint32_t pack_bf2(float a, float b) {
    __nv_bfloat162 t = __floats2bfloat162_rn(a, b);
    return *reinterpret_cast<uint32_t*>(&t);
}
__device__ __forceinline__ uint32_t pack_bb(__nv_bfloat16 a, __nv_bfloat16 b) {
    __nv_bfloat162 t(a, b);
    return *reinterpret_cast<uint32_t*>(&t);
}
__device__ __forceinline__ uint32_t split_pair(float f0, float f1, uint32_t& lo) {
    __nv_bfloat16 h0 = __float2bfloat16(f0), h1 = __float2bfloat16(f1);
    lo = pack_bf2(f0 - __bfloat162float(h0), f1 - __bfloat162float(h1));
    return pack_bb(h0, h1);
}

// ===================== prep: elementwise bf16 hi/lo split ===================
__device__ __forceinline__ void split4(const float4 v, uint32_t* oh, uint32_t* ol, int i) {
    __nv_bfloat16 h0 = __float2bfloat16(v.x), h1 = __float2bfloat16(v.y);
    __nv_bfloat16 h2 = __float2bfloat16(v.z), h3 = __float2bfloat16(v.w);
    oh[i * 2]     = pack_bb(h0, h1);
    oh[i * 2 + 1] = pack_bb(h2, h3);
    ol[i * 2]     = pack_bf2(v.x - __bfloat162float(h0), v.y - __bfloat162float(h1));
    ol[i * 2 + 1] = pack_bf2(v.z - __bfloat162float(h2), v.w - __bfloat162float(h3));
}
__global__ void prep_x_kernel(const float4* __restrict__ x) {
    int i = blockIdx.x * blockDim.x + threadIdx.x;
    split4(x[i], (uint32_t*)g_xh, (uint32_t*)g_xl, i);
}
__global__ void prep_w_kernel(const float4* __restrict__ w) {
    int i = blockIdx.x * blockDim.x + threadIdx.x;
    split4(w[i], (uint32_t*)g_wh, (uint32_t*)g_wl, i);
}
__global__ void prep_pw_kernel(const float4* __restrict__ w) {
    int i = blockIdx.x * blockDim.x + threadIdx.x;
    split4(w[i], (uint32_t*)g_pwh, (uint32_t*)g_pwl, i);
}

// ===================== Kernel 1: QKV GEMM via mma.sync (HMMA bf16) =========
#define QKV_SMEM 49152

__global__ void __launch_bounds__(256, 2) qkv_hmma_kernel(
    const float* __restrict__ bias)
{
    extern __shared__ char sm[];
    const int tid = threadIdx.x, lane = tid & 31, wid = tid >> 5;
    const int warp_m = wid & 3, warp_n = wid >> 2;
    const int j0 = blockIdx.x * 64, m0 = blockIdx.y * 128, b = blockIdx.z;

    float acc[2][4][4];
#pragma unroll
    for (int tm = 0; tm < 2; tm++)
#pragma unroll
        for (int tn = 0; tn < 4; tn++)
#pragma unroll
            for (int q = 0; q < 4; q++) acc[tm][tn][q] = 0.f;

    const uint32_t Ab = smem_u32(sm);
    const uint32_t Bb = Ab + 32768;
    const int g = lane >> 3, r8 = lane & 7;

    for (int ch = 0; ch < 8; ch++) {
        const int k0 = ch * 64;
        __syncthreads();
        {
            const __nv_bfloat16* xh = g_xh + ((size_t)(b * CH + k0)) * NTOK + m0;
            const __nv_bfloat16* xl = g_xl + ((size_t)(b * CH + k0)) * NTOK + m0;
            const __nv_bfloat16* wh = g_wh + (size_t)k0 * TC + j0;
            const __nv_bfloat16* wl = g_wl + (size_t)k0 * TC + j0;
#pragma unroll
            for (int i = 0; i < 4; i++) {
                int q = tid + i * 256, k = q >> 4, c = q & 15;
                *(int4*)(sm + k * 256 + ((c ^ (k & 7)) << 4)) =
                    *(const int4*)(xh + k * NTOK + c * 8);
            }
#pragma unroll
            for (int i = 0; i < 4; i++) {
                int q = tid + i * 256, k = q >> 4, c = q & 15;
                *(int4*)(sm + 16384 + k * 256 + ((c ^ (k & 7)) << 4)) =
                    *(const int4*)(xl + k * NTOK + c * 8);
            }
#pragma unroll
            for (int i = 0; i < 2; i++) {
                int q = tid + i * 256, k = q >> 3, c = q & 7;
                *(int4*)(sm + 32768 + k * 128 + ((c ^ (k & 7)) << 4)) =
                    *(const int4*)(wh + k * TC + c * 8);
            }
#pragma unroll
            for (int i = 0; i < 2; i++) {
                int q = tid + i * 256, k = q >> 3, c = q & 7;
                *(int4*)(sm + 40960 + k * 128 + ((c ^ (k & 7)) << 4)) =
                    *(const int4*)(wl + k * TC + c * 8);
            }
        }
        __syncthreads();

#pragma unroll
        for (int ks = 0; ks < 4; ks++) {
            uint32_t ah[2][4], al[2][4], bh[2][4], bl[2][4];
            const int klA = ks * 16 + ((g >> 1) << 3) + r8;
#pragma unroll
            for (int tm = 0; tm < 2; tm++) {
                int cc = ((warp_m * 32 + tm * 16) >> 3) + (g & 1);
                uint32_t off = klA * 256 + (((cc ^ (klA & 7))) << 4);
                ldsm4t(ah[tm], Ab + off);
                ldsm4t(al[tm], Ab + 16384 + off);
            }
            const int klB = ks * 16 + ((g & 1) << 3) + r8;
#pragma unroll
            for (int p = 0; p < 2; p++) {
                int cc = ((warp_n * 32 + p * 16) >> 3) + (g >> 1);
                uint32_t off = klB * 128 + (((cc ^ (klB & 7))) << 4);
                ldsm4t(bh[p], Bb + off);
                ldsm4t(bl[p], Bb + 8192 + off);
            }
#pragma unroll
            for (int tm = 0; tm < 2; tm++)
#pragma unroll
                for (int tn = 0; tn < 4; tn++) {
                    float* c = acc[tm][tn];
                    const uint32_t* bhp = &bh[tn >> 1][(tn & 1) * 2];
                    const uint32_t* blp = &bl[tn >> 1][(tn & 1) * 2];
                    mma16816(c, ah[tm], bhp);
                    mma16816(c, ah[tm], blp);
                    mma16816(c, al[tm], bhp);
                }
        }
    }

    const int s = j0 >> 9;
    const int h = (j0 >> 6) & (NH - 1);
    const int bhh = b * NH + h;
#pragma unroll
    for (int tn = 0; tn < 4; tn++) {
        const int d = warp_n * 32 + tn * 8 + 2 * (lane & 3);
        const float bv0 = bias[j0 + d], bv1 = bias[j0 + d + 1];
#pragma unroll
        for (int tm = 0; tm < 2; tm++) {
            const int n = m0 + warp_m * 32 + tm * 16 + (lane >> 2);
            float v0 = acc[tm][tn][0] + bv0, v1 = acc[tm][tn][1] + bv1;
            float v2 = acc[tm][tn][2] + bv0, v3 = acc[tm][tn][3] + bv1;
            if (s == 2) {
                uint32_t lo, hi;
                size_t a0 = ((size_t)bhh * NTOK + n) * HD + d;
                hi = split_pair(v0, v1, lo);
                *(uint32_t*)&g_vh[a0] = hi; *(uint32_t*)&g_vl[a0] = lo;
                size_t a1 = a0 + 8 * HD;
                hi = split_pair(v2, v3, lo);
                *(uint32_t*)&g_vh[a1] = hi; *(uint32_t*)&g_vl[a1] = lo;
            } else {
                if (s == 0) { v0 *= ATT_SCALE; v1 *= ATT_SCALE; v2 *= ATT_SCALE; v3 *= ATT_SCALE; }
                __nv_bfloat16* dh = (s == 0) ? g_qh : g_kh;
                __nv_bfloat16* dl = (s == 0) ? g_ql : g_kl;
                const size_t b0 = ((size_t)bhh * HD + d) * NTOK;
                const size_t b1 = b0 + NTOK;
                __nv_bfloat16 t;
                t = __float2bfloat16(v0); dh[b0 + n] = t; dl[b0 + n] = __float2bfloat16(v0 - __bfloat162float(t));
                t = __float2bfloat16(v1); dh[b1 + n] = t; dl[b1 + n] = __float2bfloat16(v1 - __bfloat162float(t));
                t = __float2bfloat16(v2); dh[b0 + n + 8] = t; dl[b0 + n + 8] = __float2bfloat16(v2 - __bfloat162float(t));
                t = __float2bfloat16(v3); dh[b1 + n + 8] = t; dl[b1 + n + 8] = __float2bfloat16(v3 - __bfloat162float(t));
            }
        }
    }
}

// ===================== Kernel 2: Flash attention via HMMA ===================
#define ATTN_SMEM (96 * 1024)

__global__ void __launch_bounds__(256) attn_hmma_kernel()
{
    extern __shared__ char sm[];
    const uint32_t Qh = smem_u32(sm);
    const uint32_t Ql = Qh + 16384;
    const uint32_t Kh = Qh + 32768;
    const uint32_t Kl = Qh + 49152;
    const uint32_t Vh = Qh + 65536;
    const uint32_t Vl = Qh + 81920;

    const int tid = threadIdx.x, lane = tid & 31, w = tid >> 5;
    const int g = lane >> 3, r8 = lane & 7;
    const int bh = blockIdx.x;
    const int m0 = blockIdx.y * 128;

    const __nv_bfloat16* qh = g_qh + (size_t)bh * HD * NTOK;
    const __nv_bfloat16* ql = g_ql + (size_t)bh * HD * NTOK;
    const __nv_bfloat16* kh = g_kh + (size_t)bh * HD * NTOK;
    const __nv_bfloat16* kl = g_kl + (size_t)bh * HD * NTOK;
    const __nv_bfloat16* vh = g_vh + (size_t)bh * NTOK * HD;
    const __nv_bfloat16* vl = g_vl + (size_t)bh * NTOK * HD;

#pragma unroll
    for (int i = 0; i < 4; i++) {
        int q = tid + i * 256, k = q >> 4, c = q & 15;
        uint32_t off = k * 256 + ((c ^ (k & 7)) << 4);
        *(int4*)(sm + off)         = *(const int4*)(qh + (size_t)k * NTOK + m0 + c * 8);
        *(int4*)(sm + 16384 + off) = *(const int4*)(ql + (size_t)k * NTOK + m0 + c * 8);
    }
    __syncthreads();

    uint32_t aqh[4][4], aql[4][4];
    {
        const int ccA = 2 * w + (g & 1);
#pragma unroll
        for (int ks = 0; ks < 4; ks++) {
            const int klA = ks * 16 + ((g >> 1) << 3) + r8;
            uint32_t off = klA * 256 + ((ccA ^ (klA & 7)) << 4);
            ldsm4t(aqh[ks], Qh + off);
            ldsm4t(aql[ks], Ql + off);
        }
    }

    float mr0 = -1e30f, mr1 = -1e30f, l0 = 0.f, l1 = 0.f;
    float of[8][4];
#pragma unroll
    for (int tn = 0; tn < 8; tn++)
#pragma unroll
        for (int q = 0; q < 4; q++) of[tn][q] = 0.f;

    for (int nb = 0; nb < 8; nb++) {
        const int n0 = nb * 128;
        __syncthreads();
#pragma unroll
        for (int i = 0; i < 4; i++) {
            int q = tid + i * 256, k = q >> 4, c = q & 15;
            uint32_t off = k * 256 + ((c ^ (k & 7)) << 4);
            *(int4*)(sm + 32768 + off) = *(const int4*)(kh + (size_t)k * NTOK + n0 + c * 8);
            *(int4*)(sm + 49152 + off) = *(const int4*)(kl + (size_t)k * NTOK + n0 + c * 8);
        }
#pragma unroll
        for (int i = 0; i < 4; i++) {
            int q = tid + i * 256, k = q >> 3, c = q & 7;
            uint32_t off = k * 128 + ((c ^ (k & 7)) << 4);
            *(int4*)(sm + 65536 + off) = *(const int4*)(vh + (size_t)(n0 + k) * HD + c * 8);
            *(int4*)(sm + 81920 + off) = *(const int4*)(vl + (size_t)(n0 + k) * HD + c * 8);
        }
        __syncthreads();

        float sf[16][4];
#pragma unroll
        for (int t = 0; t < 16; t++)
#pragma unroll
            for (int q = 0; q < 4; q++) sf[t][q] = 0.f;

#pragma unroll
        for (int ks = 0; ks < 4; ks++) {
            const int klB = ks * 16 + ((g & 1) << 3) + r8;
#pragma unroll
            for (int tp = 0; tp < 8; tp++) {
                uint32_t bk[4], bkl[4];
                const int cc = tp * 2 + (g >> 1);
                uint32_t off = klB * 256 + ((cc ^ (klB & 7)) << 4);
                ldsm4t(bk, Kh + off);
                ldsm4t(bkl, Kl + off);
                mma16816(sf[2 * tp],     aqh[ks], &bk[0]);
                mma16816(sf[2 * tp],     aqh[ks], &bkl[0]);
                mma16816(sf[2 * tp],     aql[ks], &bk[0]);
                mma16816(sf[2 * tp + 1], aqh[ks], &bk[2]);
                mma16816(sf[2 * tp + 1], aqh[ks], &bkl[2]);
                mma16816(sf[2 * tp + 1], aql[ks], &bk[2]);
            }
        }

        float mx0 = -1e30f, mx1 = -1e30f;
#pragma unroll
        for (int t = 0; t < 16; t++) {
            mx0 = fmaxf(mx0, fmaxf(sf[t][0], sf[t][1]));
            mx1 = fmaxf(mx1, fmaxf(sf[t][2], sf[t][3]));
        }
        mx0 = fmaxf(mx0, __shfl_xor_sync(0xffffffffu, mx0, 1));
        mx0 = fmaxf(mx0, __shfl_xor_sync(0xffffffffu, mx0, 2));
        mx1 = fmaxf(mx1, __shfl_xor_sync(0xffffffffu, mx1, 1));
        mx1 = fmaxf(mx1, __shfl_xor_sync(0xffffffffu, mx1, 2));
        const float nm0 = fmaxf(mr0, mx0), nm1 = fmaxf(mr1, mx1);
        const float a0 = __expf(mr0 - nm0), a1 = __expf(mr1 - nm1);
        mr0 = nm0; mr1 = nm1;
        float rs0 = 0.f, rs1 = 0.f;
#pragma unroll
        for (int t = 0; t < 16; t++) {
            sf[t][0] = __expf(sf[t][0] - nm0);
            sf[t][1] = __expf(sf[t][1] - nm0);
            sf[t][2] = __expf(sf[t][2] - nm1);
            sf[t][3] = __expf(sf[t][3] - nm1);
            rs0 += sf[t][0] + sf[t][1];
            rs1 += sf[t][2] + sf[t][3];
        }
        rs0 += __shfl_xor_sync(0xffffffffu, rs0, 1);
        rs0 += __shfl_xor_sync(0xffffffffu, rs0, 2);
        rs1 += __shfl_xor_sync(0xffffffffu, rs1, 1);
        rs1 += __shfl_xor_sync(0xffffffffu, rs1, 2);
        l0 = l0 * a0 + rs0;
        l1 = l1 * a1 + rs1;
#pragma unroll
        for (int tn = 0; tn < 8; tn++) {
            of[tn][0] *= a0; of[tn][1] *= a0;
            of[tn][2] *= a1; of[tn][3] *= a1;
        }

#pragma unroll
        for (int ks = 0; ks < 8; ks++) {
            uint32_t pah[4], pal[4];
            pah[0] = split_pair(sf[2 * ks][0],     sf[2 * ks][1],     pal[0]);
            pah[1] = split_pair(sf[2 * ks][2],     sf[2 * ks][3],     pal[1]);
            pah[2] = split_pair(sf[2 * ks + 1][0], sf[2 * ks + 1][1], pal[2]);
            pah[3] = split_pair(sf[2 * ks + 1][2], sf[2 * ks + 1][3], pal[3]);
            const int klV = ks * 16 + ((g & 1) << 3) + r8;
#pragma unroll
            for (int tp = 0; tp < 4; tp++) {
                uint32_t bv[4], bvl[4];
                const int cc = tp * 2 + (g >> 1);
                uint32_t off = klV * 128 + ((cc ^ (klV & 7)) << 4);
                ldsm4t(bv, Vh + off);
                ldsm4t(bvl, Vl + off);
                mma16816(of[2 * tp],     pah, &bv[0]);
                mma16816(of[2 * tp],     pah, &bvl[0]);
                mma16816(of[2 * tp],     pal, &bv[0]);
                mma16816(of[2 * tp + 1], pah, &bv[2]);
                mma16816(of[2 * tp + 1], pah, &bvl[2]);
                mma16816(of[2 * tp + 1], pal, &bv[2]);
            }
        }
    }

    // ---- normalize + write O^T bf16 hi/lo to g_oh/g_ol [b][c][n] ----
    const int b = bh >> 3, h = bh & 7;
    const float inv0 = 1.f / l0, inv1 = 1.f / l1;
    const int r = w * 16 + (lane >> 2);
    const size_t cbase = ((size_t)b * CH + h * HD) * NTOK;
#pragma unroll
    for (int tn = 0; tn < 8; tn++) {
        const int d = tn * 8 + 2 * (lane & 3);
        const size_t c0 = cbase + (size_t)d * NTOK;
        const size_t c1 = c0 + NTOK;
        float v0 = of[tn][0] * inv0, v1 = of[tn][1] * inv0;
        float v2 = of[tn][2] * inv1, v3 = of[tn][3] * inv1;
        __nv_bfloat16 t;
        const int n = m0 + r;
        t = __float2bfloat16(v0); g_oh[c0 + n] = t; g_ol[c0 + n] = __float2bfloat16(v0 - __bfloat162float(t));
        t = __float2bfloat16(v1); g_oh[c1 + n] = t; g_ol[c1 + n] = __float2bfloat16(v1 - __bfloat162float(t));
        t = __float2bfloat16(v2); g_oh[c0 + n + 8] = t; g_ol[c0 + n + 8] = __float2bfloat16(v2 - __bfloat162float(t));
        t = __float2bfloat16(v3); g_oh[c1 + n + 8] = t; g_ol[c1 + n + 8] = __float2bfloat16(v3 - __bfloat162float(t));
    }
}

// ===================== Kernel 3: Proj GEMM via mma.sync (HMMA bf16) ========
// out[b, j, n] = sum_c O^T[b,c,n] * w_proj[c,j] + bias[j]
__global__ void __launch_bounds__(256, 2) proj_hmma_kernel(
    const float* __restrict__ bias, float* __restrict__ out)
{
    extern __shared__ char sm[];
    const int tid = threadIdx.x, lane = tid & 31, wid = tid >> 5;
    const int warp_m = wid & 3, warp_n = wid >> 2;
    const int j0 = blockIdx.x * 64, m0 = blockIdx.y * 128, b = blockIdx.z;

    float acc[2][4][4];
#pragma unroll
    for (int tm = 0; tm < 2; tm++)
#pragma unroll
        for (int tn = 0; tn < 4; tn++)
#pragma unroll
            for (int q = 0; q < 4; q++) acc[tm][tn][q] = 0.f;

    const uint32_t Ab = smem_u32(sm);
    const uint32_t Bb = Ab + 32768;
    const int g = lane >> 3, r8 = lane & 7;

    for (int ch = 0; ch < 8; ch++) {
        const int k0 = ch * 64;
        __syncthreads();
        {
            const __nv_bfloat16* xh = g_oh + ((size_t)(b * CH + k0)) * NTOK + m0;
            const __nv_bfloat16* xl = g_ol + ((size_t)(b * CH + k0)) * NTOK + m0;
            const __nv_bfloat16* wh = g_pwh + (size_t)k0 * CH + j0;
            const __nv_bfloat16* wl = g_pwl + (size_t)k0 * CH + j0;
#pragma unroll
            for (int i = 0; i < 4; i++) {
                int q = tid + i * 256, k = q >> 4, c = q & 15;
                *(int4*)(sm + k * 256 + ((c ^ (k & 7)) << 4)) =
                    *(const int4*)(xh + k * NTOK + c * 8);
            }
#pragma unroll
            for (int i = 0; i < 4; i++) {
                int q = tid + i * 256, k = q >> 4, c = q & 15;
                *(int4*)(sm + 16384 + k * 256 + ((c ^ (k & 7)) << 4)) =
                    *(const int4*)(xl + k * NTOK + c * 8);
            }
#pragma unroll
            for (int i = 0; i < 2; i++) {
                int q = tid + i * 256, k = q >> 3, c = q & 7;
                *(int4*)(sm + 32768 + k * 128 + ((c ^ (k & 7)) << 4)) =
                    *(const int4*)(wh + k * CH + c * 8);
            }
#pragma unroll
            for (int i = 0; i < 2; i++) {
                int q = tid + i * 256, k = q >> 3, c = q & 7;
                *(int4*)(sm + 40960 + k * 128 + ((c ^ (k & 7)) << 4)) =
                    *(const int4*)(wl + k * CH + c * 8);
            }
        }
        __syncthreads();

#pragma unroll
        for (int ks = 0; ks < 4; ks++) {
            uint32_t ah[2][4], al[2][4], bh[2][4], bl[2][4];
            const int klA = ks * 16 + ((g >> 1) << 3) + r8;
#pragma unroll
            for (int tm = 0; tm < 2; tm++) {
                int cc = ((warp_m * 32 + tm * 16) >> 3) + (g & 1);
                uint32_t off = klA * 256 + (((cc ^ (klA & 7))) << 4);
                ldsm4t(ah[tm], Ab + off);
                ldsm4t(al[tm], Ab + 16384 + off);
            }
            const int klB = ks * 16 + ((g & 1) << 3) + r8;
#pragma unroll
            for (int p = 0; p < 2; p++) {
                int cc = ((warp_n * 32 + p * 16) >> 3) + (g >> 1);
                uint32_t off = klB * 128 + (((cc ^ (klB & 7))) << 4);
                ldsm4t(bh[p], Bb + off);
                ldsm4t(bl[p], Bb + 8192 + off);
            }
#pragma unroll
            for (int tm = 0; tm < 2; tm++)
#pragma unroll
                for (int tn = 0; tn < 4; tn++) {
                    float* c = acc[tm][tn];
                    const uint32_t* bhp = &bh[tn >> 1][(tn & 1) * 2];
                    const uint32_t* blp = &bl[tn >> 1][(tn & 1) * 2];
                    mma16816(c, ah[tm], bhp);
                    mma16816(c, ah[tm], blp);
                    mma16816(c, al[tm], bhp);
                }
        }
    }

    // ---- epilogue: out[b][j][n] (n contiguous per j) ----
    float* ob = out + (size_t)b * CH * NTOK;
#pragma unroll
    for (int tn = 0; tn < 4; tn++) {
        const int j = j0 + warp_n * 32 + tn * 8 + 2 * (lane & 3);
        const float bv0 = bias[j], bv1 = bias[j + 1];
        float* p0 = ob + (size_t)j * NTOK;
        float* p1 = p0 + NTOK;
#pragma unroll
        for (int tm = 0; tm < 2; tm++) {
            const int n = m0 + warp_m * 32 + tm * 16 + (lane >> 2);
            p0[n]     = acc[tm][tn][0] + bv0;
            p1[n]     = acc[tm][tn][1] + bv1;
            p0[n + 8] = acc[tm][tn][2] + bv0;
            p1[n + 8] = acc[tm][tn][3] + bv1;
        }
    }
}

// ---------------------------------------------------------------------------
extern "C" void kernel_launch(void* const* d_in, const int* in_sizes, int n_in,
                              void* d_out, int out_size)
{
    const float* x      = (const float*)d_in[0];
    const float* w_qkv  = (const float*)d_in[1];
    const float* b_qkv  = (const float*)d_in[2];
    const float* w_proj = (const float*)d_in[3];
    const float* b_proj = (const float*)d_in[4];
    float* out = (float*)d_out;

    cudaFuncSetAttribute(qkv_hmma_kernel,
                         cudaFuncAttributeMaxDynamicSharedMemorySize, QKV_SMEM);
    cudaFuncSetAttribute(attn_hmma_kernel,
                         cudaFuncAttributeMaxDynamicSharedMemorySize, ATTN_SMEM);
    cudaFuncSetAttribute(proj_hmma_kernel,
                         cudaFuncAttributeMaxDynamicSharedMemorySize, QKV_SMEM);

    prep_x_kernel<<<(BATCH * CH * NTOK / 4) / 256, 256>>>((const float4*)x);
    prep_w_kernel<<<(CH * TC / 4) / 256, 256>>>((const float4*)w_qkv);
    prep_pw_kernel<<<(CH * CH / 4) / 256, 256>>>((const float4*)w_proj);
    qkv_hmma_kernel<<<dim3(TC / 64, NTOK / 128, BATCH), 256, QKV_SMEM>>>(b_qkv);
    attn_hmma_kernel<<<dim3(BATCH * NH, NTOK / 128), 256, ATTN_SMEM>>>();
    proj_hmma_kernel<<<dim3(CH / 64, NTOK / 128, BATCH), 256, QKV_SMEM>>>(b_proj, out);
}

// round 10
// speedup vs baseline: 3.2060x; 1.1514x over previous
#include <cuda_runtime.h>
#include <cuda_bf16.h>
#include <cstdint>

#define BATCH 8
#define CH    512
#define NTOK  1024
#define NH    8
#define HD    64
#define TC    1536
#define ATT_SCALE 0.125f

// bf16 hi/lo split inputs (original layouts)
__device__ __align__(16) __nv_bfloat16 g_xh[BATCH * CH * NTOK];  // [b][k][m]
__device__ __align__(16) __nv_bfloat16 g_xl[BATCH * CH * NTOK];
__device__ __align__(16) __nv_bfloat16 g_wh[CH * TC];            // [k][j]
__device__ __align__(16) __nv_bfloat16 g_wl[CH * TC];
__device__ __align__(16) __nv_bfloat16 g_pwh[CH * CH];           // [c][j]
__device__ __align__(16) __nv_bfloat16 g_pwl[CH * CH];

// attention operands, written by QKV epilogue
__device__ __align__(16) __nv_bfloat16 g_qh[BATCH * NH * HD * NTOK]; // [b][h][d][n], pre-scaled
__device__ __align__(16) __nv_bfloat16 g_ql[BATCH * NH * HD * NTOK];
__device__ __align__(16) __nv_bfloat16 g_kh[BATCH * NH * HD * NTOK]; // [b][h][d][n]
__device__ __align__(16) __nv_bfloat16 g_kl[BATCH * NH * HD * NTOK];
__device__ __align__(16) __nv_bfloat16 g_vh[BATCH * NH * NTOK * HD]; // [b][h][n][d]
__device__ __align__(16) __nv_bfloat16 g_vl[BATCH * NH * NTOK * HD];
// attention output, transposed, bf16 hi/lo: [b][c][n]
__device__ __align__(16) __nv_bfloat16 g_oh[BATCH * CH * NTOK];
__device__ __align__(16) __nv_bfloat16 g_ol[BATCH * CH * NTOK];

__device__ __forceinline__ uint32_t smem_u32(const void* p) {
    uint32_t a;
    asm("{ .reg .u64 t; cvta.to.shared.u64 t, %1; cvt.u32.u64 %0, t; }"
        : "=r"(a) : "l"(p));
    return a;
}
__device__ __forceinline__ void cp16(uint32_t dst, const void* src) {
    asm volatile("cp.async.cg.shared.global [%0], [%1], 16;"
                 :: "r"(dst), "l"(src));
}
#define CP_COMMIT() asm volatile("cp.async.commit_group;" ::: "memory")
#define CP_WAIT1()  asm volatile("cp.async.wait_group 1;" ::: "memory")
#define CP_WAIT0()  asm volatile("cp.async.wait_group 0;" ::: "memory")

__device__ __forceinline__ void ldsm4t(uint32_t* r, uint32_t a) {
    asm volatile("ldmatrix.sync.aligned.m8n8.x4.trans.shared.b16 {%0,%1,%2,%3}, [%4];"
                 : "=r"(r[0]), "=r"(r[1]), "=r"(r[2]), "=r"(r[3]) : "r"(a));
}
__device__ __forceinline__ void mma16816(float* c, const uint32_t* a, const uint32_t* b) {
    asm volatile(
        "mma.sync.aligned.m16n8k16.row.col.f32.bf16.bf16.f32 "
        "{%0,%1,%2,%3}, {%4,%5,%6,%7}, {%8,%9}, {%0,%1,%2,%3};"
        : "+f"(c[0]), "+f"(c[1]), "+f"(c[2]), "+f"(c[3])
        : "r"(a[0]), "r"(a[1]), "r"(a[2]), "r"(a[3]), "r"(b[0]), "r"(b[1]));
}
__device__ __forceinline__ uint32_t pack_bf2(float a, float b) {
    __nv_bfloat162 t = __floats2bfloat162_rn(a, b);
    return *reinterpret_cast<uint32_t*>(&t);
}
__device__ __forceinline__ uint32_t pack_bb(__nv_bfloat16 a, __nv_bfloat16 b) {
    __nv_bfloat162 t(a, b);
    return *reinterpret_cast<uint32_t*>(&t);
}
__device__ __forceinline__ uint32_t split_pair(float f0, float f1, uint32_t& lo) {
    __nv_bfloat16 h0 = __float2bfloat16(f0), h1 = __float2bfloat16(f1);
    lo = pack_bf2(f0 - __bfloat162float(h0), f1 - __bfloat162float(h1));
    return pack_bb(h0, h1);
}

// ===================== prep: elementwise bf16 hi/lo split ===================
__device__ __forceinline__ void split4(const float4 v, uint32_t* oh, uint32_t* ol, int i) {
    __nv_bfloat16 h0 = __float2bfloat16(v.x), h1 = __float2bfloat16(v.y);
    __nv_bfloat16 h2 = __float2bfloat16(v.z), h3 = __float2bfloat16(v.w);
    oh[i * 2]     = pack_bb(h0, h1);
    oh[i * 2 + 1] = pack_bb(h2, h3);
    ol[i * 2]     = pack_bf2(v.x - __bfloat162float(h0), v.y - __bfloat162float(h1));
    ol[i * 2 + 1] = pack_bf2(v.z - __bfloat162float(h2), v.w - __bfloat162float(h3));
}
__global__ void prep_x_kernel(const float4* __restrict__ x) {
    int i = blockIdx.x * blockDim.x + threadIdx.x;
    split4(x[i], (uint32_t*)g_xh, (uint32_t*)g_xl, i);
}
__global__ void prep_w_kernel(const float4* __restrict__ w) {
    int i = blockIdx.x * blockDim.x + threadIdx.x;
    split4(w[i], (uint32_t*)g_wh, (uint32_t*)g_wl, i);
}
__global__ void prep_pw_kernel(const float4* __restrict__ w) {
    int i = blockIdx.x * blockDim.x + threadIdx.x;
    split4(w[i], (uint32_t*)g_pwh, (uint32_t*)g_pwl, i);
}

// ============ GEMM body (shared by qkv & proj): cp.async pipelined =========
// Stage (24 KB): Ah[32][256B] +0, Al +8192, Bh[32][128B] +16384, Bl +20480.
// A is [k][token] (256B rows), B is [k][j] (128B rows), K-chunks of 32.
__device__ __forceinline__ void gemm_copy_stage(
    uint32_t St, const __nv_bfloat16* xh, const __nv_bfloat16* xl,
    const __nv_bfloat16* wh, const __nv_bfloat16* wl,
    int k0, int wstride, int tid)
{
#pragma unroll
    for (int i = 0; i < 2; i++) {
        int q = tid + i * 256, k = q >> 4, c = q & 15;
        uint32_t off = k * 256 + ((c ^ (k & 7)) << 4);
        cp16(St + off,        xh + (size_t)(k0 + k) * NTOK + c * 8);
        cp16(St + 8192 + off, xl + (size_t)(k0 + k) * NTOK + c * 8);
    }
    {
        int k = tid >> 3, c = tid & 7;
        uint32_t off = k * 128 + ((c ^ (k & 7)) << 4);
        cp16(St + 16384 + off, wh + (size_t)(k0 + k) * wstride + c * 8);
        cp16(St + 20480 + off, wl + (size_t)(k0 + k) * wstride + c * 8);
    }
}

__device__ __forceinline__ void gemm_pipeline(
    char* sm, const __nv_bfloat16* xh, const __nv_bfloat16* xl,
    const __nv_bfloat16* wh, const __nv_bfloat16* wl,
    int wstride, float acc[2][4][4],
    int tid, int lane, int warp_m, int warp_n)
{
    const uint32_t sb = smem_u32(sm);
    const int g = lane >> 3, r8 = lane & 7;

    gemm_copy_stage(sb, xh, xl, wh, wl, 0, wstride, tid);
    CP_COMMIT();

    for (int ch = 0; ch < 16; ch++) {
        const uint32_t St = sb + (ch & 1) * 24576;
        if (ch < 15) {
            gemm_copy_stage(sb + ((ch + 1) & 1) * 24576, xh, xl, wh, wl,
                            (ch + 1) * 32, wstride, tid);
            CP_COMMIT();
            CP_WAIT1();
        } else {
            CP_WAIT0();
        }
        __syncthreads();

#pragma unroll
        for (int ks = 0; ks < 2; ks++) {
            uint32_t ah[2][4], al[2][4], bh[2][4], bl[2][4];
            const int klA = ks * 16 + ((g >> 1) << 3) + r8;
#pragma unroll
            for (int tm = 0; tm < 2; tm++) {
                int cc = ((warp_m * 32 + tm * 16) >> 3) + (g & 1);
                uint32_t off = klA * 256 + ((cc ^ (klA & 7)) << 4);
                ldsm4t(ah[tm], St + off);
                ldsm4t(al[tm], St + 8192 + off);
            }
            const int klB = ks * 16 + ((g & 1) << 3) + r8;
#pragma unroll
            for (int p = 0; p < 2; p++) {
                int cc = ((warp_n * 32 + p * 16) >> 3) + (g >> 1);
                uint32_t off = klB * 128 + ((cc ^ (klB & 7)) << 4);
                ldsm4t(bh[p], St + 16384 + off);
                ldsm4t(bl[p], St + 20480 + off);
            }
#pragma unroll
            for (int tm = 0; tm < 2; tm++)
#pragma unroll
                for (int tn = 0; tn < 4; tn++) {
                    float* c = acc[tm][tn];
                    const uint32_t* bhp = &bh[tn >> 1][(tn & 1) * 2];
                    const uint32_t* blp = &bl[tn >> 1][(tn & 1) * 2];
                    mma16816(c, ah[tm], bhp);
                    mma16816(c, ah[tm], blp);
                    mma16816(c, al[tm], bhp);
                }
        }
        __syncthreads();
    }
}

// ===================== Kernel 1: QKV GEMM ==================================
#define GEMM_SMEM 49152

__global__ void __launch_bounds__(256, 2) qkv_hmma_kernel(
    const float* __restrict__ bias)
{
    extern __shared__ char sm[];
    const int tid = threadIdx.x, lane = tid & 31, wid = tid >> 5;
    const int warp_m = wid & 3, warp_n = wid >> 2;
    const int j0 = blockIdx.x * 64, m0 = blockIdx.y * 128, b = blockIdx.z;

    float acc[2][4][4];
#pragma unroll
    for (int tm = 0; tm < 2; tm++)
#pragma unroll
        for (int tn = 0; tn < 4; tn++)
#pragma unroll
            for (int q = 0; q < 4; q++) acc[tm][tn][q] = 0.f;

    gemm_pipeline(sm,
                  g_xh + (size_t)b * CH * NTOK + m0,
                  g_xl + (size_t)b * CH * NTOK + m0,
                  g_wh + j0, g_wl + j0, TC, acc, tid, lane, warp_m, warp_n);

    const int s = j0 >> 9;
    const int h = (j0 >> 6) & (NH - 1);
    const int bhh = b * NH + h;
#pragma unroll
    for (int tn = 0; tn < 4; tn++) {
        const int d = warp_n * 32 + tn * 8 + 2 * (lane & 3);
        const float bv0 = bias[j0 + d], bv1 = bias[j0 + d + 1];
#pragma unroll
        for (int tm = 0; tm < 2; tm++) {
            const int n = m0 + warp_m * 32 + tm * 16 + (lane >> 2);
            float v0 = acc[tm][tn][0] + bv0, v1 = acc[tm][tn][1] + bv1;
            float v2 = acc[tm][tn][2] + bv0, v3 = acc[tm][tn][3] + bv1;
            if (s == 2) {
                uint32_t lo, hi;
                size_t a0 = ((size_t)bhh * NTOK + n) * HD + d;
                hi = split_pair(v0, v1, lo);
                *(uint32_t*)&g_vh[a0] = hi; *(uint32_t*)&g_vl[a0] = lo;
                size_t a1 = a0 + 8 * HD;
                hi = split_pair(v2, v3, lo);
                *(uint32_t*)&g_vh[a1] = hi; *(uint32_t*)&g_vl[a1] = lo;
            } else {
                if (s == 0) { v0 *= ATT_SCALE; v1 *= ATT_SCALE; v2 *= ATT_SCALE; v3 *= ATT_SCALE; }
                __nv_bfloat16* dh = (s == 0) ? g_qh : g_kh;
                __nv_bfloat16* dl = (s == 0) ? g_ql : g_kl;
                const size_t b0 = ((size_t)bhh * HD + d) * NTOK;
                const size_t b1 = b0 + NTOK;
                __nv_bfloat16 t;
                t = __float2bfloat16(v0); dh[b0 + n] = t; dl[b0 + n] = __float2bfloat16(v0 - __bfloat162float(t));
                t = __float2bfloat16(v1); dh[b1 + n] = t; dl[b1 + n] = __float2bfloat16(v1 - __bfloat162float(t));
                t = __float2bfloat16(v2); dh[b0 + n + 8] = t; dl[b0 + n + 8] = __float2bfloat16(v2 - __bfloat162float(t));
                t = __float2bfloat16(v3); dh[b1 + n + 8] = t; dl[b1 + n + 8] = __float2bfloat16(v3 - __bfloat162float(t));
            }
        }
    }
}

// ===================== Kernel 2: Flash attention (cp.async K/V) =============
// smem: Qh 0, Ql 16384; stage s at 32768 + s*65536:
//   Kh +0, Kl +16384, Vh +32768, Vl +49152.  Total 160 KB.
#define ATTN_SMEM (160 * 1024)

__device__ __forceinline__ void attn_copy_stage(
    uint32_t St, const __nv_bfloat16* kh, const __nv_bfloat16* kl,
    const __nv_bfloat16* vh, const __nv_bfloat16* vl, int n0, int tid)
{
#pragma unroll
    for (int i = 0; i < 4; i++) {
        int q = tid + i * 256, k = q >> 4, c = q & 15;     // K: 64 rows x 16
        uint32_t off = k * 256 + ((c ^ (k & 7)) << 4);
        cp16(St + off,         kh + (size_t)k * NTOK + n0 + c * 8);
        cp16(St + 16384 + off, kl + (size_t)k * NTOK + n0 + c * 8);
    }
#pragma unroll
    for (int i = 0; i < 4; i++) {
        int q = tid + i * 256, k = q >> 3, c = q & 7;      // V: 128 rows x 8
        uint32_t off = k * 128 + ((c ^ (k & 7)) << 4);
        cp16(St + 32768 + off, vh + (size_t)(n0 + k) * HD + c * 8);
        cp16(St + 49152 + off, vl + (size_t)(n0 + k) * HD + c * 8);
    }
}

__global__ void __launch_bounds__(256) attn_hmma_kernel()
{
    extern __shared__ char sm[];
    const uint32_t Qh = smem_u32(sm);
    const uint32_t Ql = Qh + 16384;

    const int tid = threadIdx.x, lane = tid & 31, w = tid >> 5;
    const int g = lane >> 3, r8 = lane & 7;
    const int bh = blockIdx.x;
    const int m0 = blockIdx.y * 128;

    const __nv_bfloat16* qh = g_qh + (size_t)bh * HD * NTOK;
    const __nv_bfloat16* ql = g_ql + (size_t)bh * HD * NTOK;
    const __nv_bfloat16* kh = g_kh + (size_t)bh * HD * NTOK;
    const __nv_bfloat16* kl = g_kl + (size_t)bh * HD * NTOK;
    const __nv_bfloat16* vh = g_vh + (size_t)bh * NTOK * HD;
    const __nv_bfloat16* vl = g_vl + (size_t)bh * NTOK * HD;

    // prefetch KV block 0 while loading Q
    attn_copy_stage(Qh + 32768, kh, kl, vh, vl, 0, tid);
    CP_COMMIT();

#pragma unroll
    for (int i = 0; i < 4; i++) {
        int q = tid + i * 256, k = q >> 4, c = q & 15;
        uint32_t off = k * 256 + ((c ^ (k & 7)) << 4);
        *(int4*)(sm + off)         = *(const int4*)(qh + (size_t)k * NTOK + m0 + c * 8);
        *(int4*)(sm + 16384 + off) = *(const int4*)(ql + (size_t)k * NTOK + m0 + c * 8);
    }
    __syncthreads();

    uint32_t aqh[4][4], aql[4][4];
    {
        const int ccA = 2 * w + (g & 1);
#pragma unroll
        for (int ks = 0; ks < 4; ks++) {
            const int klA = ks * 16 + ((g >> 1) << 3) + r8;
            uint32_t off = klA * 256 + ((ccA ^ (klA & 7)) << 4);
            ldsm4t(aqh[ks], Qh + off);
            ldsm4t(aql[ks], Ql + off);
        }
    }

    float mr0 = -1e30f, mr1 = -1e30f, l0 = 0.f, l1 = 0.f;
    float of[8][4];
#pragma unroll
    for (int tn = 0; tn < 8; tn++)
#pragma unroll
        for (int q = 0; q < 4; q++) of[tn][q] = 0.f;

    for (int nb = 0; nb < 8; nb++) {
        const uint32_t St = Qh + 32768 + (nb & 1) * 65536;
        if (nb < 7) {
            attn_copy_stage(Qh + 32768 + ((nb + 1) & 1) * 65536,
                            kh, kl, vh, vl, (nb + 1) * 128, tid);
            CP_COMMIT();
            CP_WAIT1();
        } else {
            CP_WAIT0();
        }
        __syncthreads();

        const uint32_t Kh = St, Kl = St + 16384;
        const uint32_t Vh = St + 32768, Vl = St + 49152;

        float sf[16][4];
#pragma unroll
        for (int t = 0; t < 16; t++)
#pragma unroll
            for (int q = 0; q < 4; q++) sf[t][q] = 0.f;

#pragma unroll
        for (int ks = 0; ks < 4; ks++) {
            const int klB = ks * 16 + ((g & 1) << 3) + r8;
#pragma unroll
            for (int tp = 0; tp < 8; tp++) {
                uint32_t bk[4], bkl[4];
                const int cc = tp * 2 + (g >> 1);
                uint32_t off = klB * 256 + ((cc ^ (klB & 7)) << 4);
                ldsm4t(bk, Kh + off);
                ldsm4t(bkl, Kl + off);
                mma16816(sf[2 * tp],     aqh[ks], &bk[0]);
                mma16816(sf[2 * tp],     aqh[ks], &bkl[0]);
                mma16816(sf[2 * tp],     aql[ks], &bk[0]);
                mma16816(sf[2 * tp + 1], aqh[ks], &bk[2]);
                mma16816(sf[2 * tp + 1], aqh[ks], &bkl[2]);
                mma16816(sf[2 * tp + 1], aql[ks], &bk[2]);
            }
        }

        float mx0 = -1e30f, mx1 = -1e30f;
#pragma unroll
        for (int t = 0; t < 16; t++) {
            mx0 = fmaxf(mx0, fmaxf(sf[t][0], sf[t][1]));
            mx1 = fmaxf(mx1, fmaxf(sf[t][2], sf[t][3]));
        }
        mx0 = fmaxf(mx0, __shfl_xor_sync(0xffffffffu, mx0, 1));
        mx0 = fmaxf(mx0, __shfl_xor_sync(0xffffffffu, mx0, 2));
        mx1 = fmaxf(mx1, __shfl_xor_sync(0xffffffffu, mx1, 1));
        mx1 = fmaxf(mx1, __shfl_xor_sync(0xffffffffu, mx1, 2));
        const float nm0 = fmaxf(mr0, mx0), nm1 = fmaxf(mr1, mx1);
        const float a0 = __expf(mr0 - nm0), a1 = __expf(mr1 - nm1);
        mr0 = nm0; mr1 = nm1;
        float rs0 = 0.f, rs1 = 0.f;
#pragma unroll
        for (int t = 0; t < 16; t++) {
            sf[t][0] = __expf(sf[t][0] - nm0);
            sf[t][1] = __expf(sf[t][1] - nm0);
            sf[t][2] = __expf(sf[t][2] - nm1);
            sf[t][3] = __expf(sf[t][3] - nm1);
            rs0 += sf[t][0] + sf[t][1];
            rs1 += sf[t][2] + sf[t][3];
        }
        rs0 += __shfl_xor_sync(0xffffffffu, rs0, 1);
        rs0 += __shfl_xor_sync(0xffffffffu, rs0, 2);
        rs1 += __shfl_xor_sync(0xffffffffu, rs1, 1);
        rs1 += __shfl_xor_sync(0xffffffffu, rs1, 2);
        l0 = l0 * a0 + rs0;
        l1 = l1 * a1 + rs1;
#pragma unroll
        for (int tn = 0; tn < 8; tn++) {
            of[tn][0] *= a0; of[tn][1] *= a0;
            of[tn][2] *= a1; of[tn][3] *= a1;
        }

#pragma unroll
        for (int ks = 0; ks < 8; ks++) {
            uint32_t pah[4], pal[4];
            pah[0] = split_pair(sf[2 * ks][0],     sf[2 * ks][1],     pal[0]);
            pah[1] = split_pair(sf[2 * ks][2],     sf[2 * ks][3],     pal[1]);
            pah[2] = split_pair(sf[2 * ks + 1][0], sf[2 * ks + 1][1], pal[2]);
            pah[3] = split_pair(sf[2 * ks + 1][2], sf[2 * ks + 1][3], pal[3]);
            const int klV = ks * 16 + ((g & 1) << 3) + r8;
#pragma unroll
            for (int tp = 0; tp < 4; tp++) {
                uint32_t bv[4], bvl[4];
                const int cc = tp * 2 + (g >> 1);
                uint32_t off = klV * 128 + ((cc ^ (klV & 7)) << 4);
                ldsm4t(bv, Vh + off);
                ldsm4t(bvl, Vl + off);
                mma16816(of[2 * tp],     pah, &bv[0]);
                mma16816(of[2 * tp],     pah, &bvl[0]);
                mma16816(of[2 * tp],     pal, &bv[0]);
                mma16816(of[2 * tp + 1], pah, &bv[2]);
                mma16816(of[2 * tp + 1], pah, &bvl[2]);
                mma16816(of[2 * tp + 1], pal, &bv[2]);
            }
        }
        __syncthreads();
    }

    const int b = bh >> 3, h = bh & 7;
    const float inv0 = 1.f / l0, inv1 = 1.f / l1;
    const int r = w * 16 + (lane >> 2);
    const size_t cbase = ((size_t)b * CH + h * HD) * NTOK;
#pragma unroll
    for (int tn = 0; tn < 8; tn++) {
        const int d = tn * 8 + 2 * (lane & 3);
        const size_t c0 = cbase + (size_t)d * NTOK;
        const size_t c1 = c0 + NTOK;
        float v0 = of[tn][0] * inv0, v1 = of[tn][1] * inv0;
        float v2 = of[tn][2] * inv1, v3 = of[tn][3] * inv1;
        __nv_bfloat16 t;
        const int n = m0 + r;
        t = __float2bfloat16(v0); g_oh[c0 + n] = t; g_ol[c0 + n] = __float2bfloat16(v0 - __bfloat162float(t));
        t = __float2bfloat16(v1); g_oh[c1 + n] = t; g_ol[c1 + n] = __float2bfloat16(v1 - __bfloat162float(t));
        t = __float2bfloat16(v2); g_oh[c0 + n + 8] = t; g_ol[c0 + n + 8] = __float2bfloat16(v2 - __bfloat162float(t));
        t = __float2bfloat16(v3); g_oh[c1 + n + 8] = t; g_ol[c1 + n + 8] = __float2bfloat16(v3 - __bfloat162float(t));
    }
}

// ===================== Kernel 3: Proj GEMM =================================
__global__ void __launch_bounds__(256, 2) proj_hmma_kernel(
    const float* __restrict__ bias, float* __restrict__ out)
{
    extern __shared__ char sm[];
    const int tid = threadIdx.x, lane = tid & 31, wid = tid >> 5;
    const int warp_m = wid & 3, warp_n = wid >> 2;
    const int j0 = blockIdx.x * 64, m0 = blockIdx.y * 128, b = blockIdx.z;

    float acc[2][4][4];
#pragma unroll
    for (int tm = 0; tm < 2; tm++)
#pragma unroll
        for (int tn = 0; tn < 4; tn++)
#pragma unroll
            for (int q = 0; q < 4; q++) acc[tm][tn][q] = 0.f;

    gemm_pipeline(sm,
                  g_oh + (size_t)b * CH * NTOK + m0,
                  g_ol + (size_t)b * CH * NTOK + m0,
                  g_pwh + j0, g_pwl + j0, CH, acc, tid, lane, warp_m, warp_n);

    float* ob = out + (size_t)b * CH * NTOK;
#pragma unroll
    for (int tn = 0; tn < 4; tn++) {
        const int j = j0 + warp_n * 32 + tn * 8 + 2 * (lane & 3);
        const float bv0 = bias[j], bv1 = bias[j + 1];
        float* p0 = ob + (size_t)j * NTOK;
        float* p1 = p0 + NTOK;
#pragma unroll
        for (int tm = 0; tm < 2; tm++) {
            const int n = m0 + warp_m * 32 + tm * 16 + (lane >> 2);
            p0[n]     = acc[tm][tn][0] + bv0;
            p1[n]     = acc[tm][tn][1] + bv1;
            p0[n + 8] = acc[tm][tn][2] + bv0;
            p1[n + 8] = acc[tm][tn][3] + bv1;
        }
    }
}

// ---------------------------------------------------------------------------
extern "C" void kernel_launch(void* const* d_in, const int* in_sizes, int n_in,
                              void* d_out, int out_size)
{
    const float* x      = (const float*)d_in[0];
    const float* w_qkv  = (const float*)d_in[1];
    const float* b_qkv  = (const float*)d_in[2];
    const float* w_proj = (const float*)d_in[3];
    const float* b_proj = (const float*)d_in[4];
    float* out = (float*)d_out;

    cudaFuncSetAttribute(qkv_hmma_kernel,
                         cudaFuncAttributeMaxDynamicSharedMemorySize, GEMM_SMEM);
    cudaFuncSetAttribute(attn_hmma_kernel,
                         cudaFuncAttributeMaxDynamicSharedMemorySize, ATTN_SMEM);
    cudaFuncSetAttribute(proj_hmma_kernel,
                         cudaFuncAttributeMaxDynamicSharedMemorySize, GEMM_SMEM);

    prep_x_kernel<<<(BATCH * CH * NTOK / 4) / 256, 256>>>((const float4*)x);
    prep_w_kernel<<<(CH * TC / 4) / 256, 256>>>((const float4*)w_qkv);
    prep_pw_kernel<<<(CH * CH / 4) / 256, 256>>>((const float4*)w_proj);
    qkv_hmma_kernel<<<dim3(TC / 64, NTOK / 128, BATCH), 256, GEMM_SMEM>>>(b_qkv);
    attn_hmma_kernel<<<dim3(BATCH * NH, NTOK / 128), 256, ATTN_SMEM>>>();
    proj_hmma_kernel<<<dim3(CH / 64, NTOK / 128, BATCH), 256, GEMM_SMEM>>>(b_proj, out);
}

// round 11
// speedup vs baseline: 6.8328x; 2.1313x over previous
#include <cuda_runtime.h>
#include <cuda_fp16.h>
#include <cstdint>

#define BATCH 8
#define CH    512
#define NTOK  1024
#define NH    8
#define HD    64
#define TC    1536
#define ATT_SCALE 0.125f

// fp16 inputs (original layouts)
__device__ __align__(16) __half g_x[BATCH * CH * NTOK];   // [b][k][m]
__device__ __align__(16) __half g_w[CH * TC];             // [k][j]
__device__ __align__(16) __half g_pw[CH * CH];            // [c][j]

// attention operands, written by QKV epilogue
__device__ __align__(16) __half g_q[BATCH * NH * HD * NTOK]; // [b][h][d][n], pre-scaled
__device__ __align__(16) __half g_k[BATCH * NH * HD * NTOK]; // [b][h][d][n]
__device__ __align__(16) __half g_v[BATCH * NH * NTOK * HD]; // [b][h][n][d]
// attention output, transposed: [b][c][n]
__device__ __align__(16) __half g_o[BATCH * CH * NTOK];

__device__ __forceinline__ uint32_t smem_u32(const void* p) {
    uint32_t a;
    asm("{ .reg .u64 t; cvta.to.shared.u64 t, %1; cvt.u32.u64 %0, t; }"
        : "=r"(a) : "l"(p));
    return a;
}
__device__ __forceinline__ void cp16(uint32_t dst, const void* src) {
    asm volatile("cp.async.cg.shared.global [%0], [%1], 16;"
                 :: "r"(dst), "l"(src));
}
#define CP_COMMIT() asm volatile("cp.async.commit_group;" ::: "memory")
#define CP_WAIT1()  asm volatile("cp.async.wait_group 1;" ::: "memory")
#define CP_WAIT0()  asm volatile("cp.async.wait_group 0;" ::: "memory")

__device__ __forceinline__ void ldsm4t(uint32_t* r, uint32_t a) {
    asm volatile("ldmatrix.sync.aligned.m8n8.x4.trans.shared.b16 {%0,%1,%2,%3}, [%4];"
                 : "=r"(r[0]), "=r"(r[1]), "=r"(r[2]), "=r"(r[3]) : "r"(a));
}
__device__ __forceinline__ void mma16816(float* c, const uint32_t* a, const uint32_t* b) {
    asm volatile(
        "mma.sync.aligned.m16n8k16.row.col.f32.f16.f16.f32 "
        "{%0,%1,%2,%3}, {%4,%5,%6,%7}, {%8,%9}, {%0,%1,%2,%3};"
        : "+f"(c[0]), "+f"(c[1]), "+f"(c[2]), "+f"(c[3])
        : "r"(a[0]), "r"(a[1]), "r"(a[2]), "r"(a[3]), "r"(b[0]), "r"(b[1]));
}
__device__ __forceinline__ uint32_t pack_hh(float a, float b) {
    __half2 t = __floats2half2_rn(a, b);
    return *reinterpret_cast<uint32_t*>(&t);
}

// ===================== prep: fp32 -> fp16 ===================================
__device__ __forceinline__ void cvt4(const float4 v, uint32_t* o, int i) {
    o[i * 2]     = pack_hh(v.x, v.y);
    o[i * 2 + 1] = pack_hh(v.z, v.w);
}
__global__ void prep_x_kernel(const float4* __restrict__ x) {
    int i = blockIdx.x * blockDim.x + threadIdx.x;
    cvt4(x[i], (uint32_t*)g_x, i);
}
__global__ void prep_w_kernel(const float4* __restrict__ w) {
    int i = blockIdx.x * blockDim.x + threadIdx.x;
    cvt4(w[i], (uint32_t*)g_w, i);
}
__global__ void prep_pw_kernel(const float4* __restrict__ w) {
    int i = blockIdx.x * blockDim.x + threadIdx.x;
    cvt4(w[i], (uint32_t*)g_pw, i);
}

// ============ GEMM body (qkv & proj): cp.async pipelined, fp16 =============
// Stage (12 KB): A[32][256B] +0, B[32][128B] +8192.  K-chunks of 32, double-buf.
__device__ __forceinline__ void gemm_copy_stage(
    uint32_t St, const __half* x, const __half* w,
    int k0, int wstride, int tid)
{
#pragma unroll
    for (int i = 0; i < 2; i++) {
        int q = tid + i * 256, k = q >> 4, c = q & 15;
        uint32_t off = k * 256 + ((c ^ (k & 7)) << 4);
        cp16(St + off, x + (size_t)(k0 + k) * NTOK + c * 8);
    }
    {
        int k = tid >> 3, c = tid & 7;
        uint32_t off = k * 128 + ((c ^ (k & 7)) << 4);
        cp16(St + 8192 + off, w + (size_t)(k0 + k) * wstride + c * 8);
    }
}

__device__ __forceinline__ void gemm_pipeline(
    char* sm, const __half* x, const __half* w,
    int wstride, float acc[2][4][4],
    int tid, int lane, int warp_m, int warp_n)
{
    const uint32_t sb = smem_u32(sm);
    const int g = lane >> 3, r8 = lane & 7;

    gemm_copy_stage(sb, x, w, 0, wstride, tid);
    CP_COMMIT();

    for (int ch = 0; ch < 16; ch++) {
        const uint32_t St = sb + (ch & 1) * 12288;
        if (ch < 15) {
            gemm_copy_stage(sb + ((ch + 1) & 1) * 12288, x, w,
                            (ch + 1) * 32, wstride, tid);
            CP_COMMIT();
            CP_WAIT1();
        } else {
            CP_WAIT0();
        }
        __syncthreads();

#pragma unroll
        for (int ks = 0; ks < 2; ks++) {
            uint32_t a[2][4], bb[2][4];
            const int klA = ks * 16 + ((g >> 1) << 3) + r8;
#pragma unroll
            for (int tm = 0; tm < 2; tm++) {
                int cc = ((warp_m * 32 + tm * 16) >> 3) + (g & 1);
                uint32_t off = klA * 256 + ((cc ^ (klA & 7)) << 4);
                ldsm4t(a[tm], St + off);
            }
            const int klB = ks * 16 + ((g & 1) << 3) + r8;
#pragma unroll
            for (int p = 0; p < 2; p++) {
                int cc = ((warp_n * 32 + p * 16) >> 3) + (g >> 1);
                uint32_t off = klB * 128 + ((cc ^ (klB & 7)) << 4);
                ldsm4t(bb[p], St + 8192 + off);
            }
#pragma unroll
            for (int tm = 0; tm < 2; tm++)
#pragma unroll
                for (int tn = 0; tn < 4; tn++)
                    mma16816(acc[tm][tn], a[tm], &bb[tn >> 1][(tn & 1) * 2]);
        }
        __syncthreads();
    }
}

// ===================== Kernel 1: QKV GEMM ==================================
#define GEMM_SMEM 24576

__global__ void __launch_bounds__(256, 2) qkv_hmma_kernel(
    const float* __restrict__ bias)
{
    extern __shared__ char sm[];
    const int tid = threadIdx.x, lane = tid & 31, wid = tid >> 5;
    const int warp_m = wid & 3, warp_n = wid >> 2;
    const int j0 = blockIdx.x * 64, m0 = blockIdx.y * 128, b = blockIdx.z;

    float acc[2][4][4];
#pragma unroll
    for (int tm = 0; tm < 2; tm++)
#pragma unroll
        for (int tn = 0; tn < 4; tn++)
#pragma unroll
            for (int q = 0; q < 4; q++) acc[tm][tn][q] = 0.f;

    gemm_pipeline(sm, g_x + (size_t)b * CH * NTOK + m0,
                  g_w + j0, TC, acc, tid, lane, warp_m, warp_n);

    const int s = j0 >> 9;
    const int h = (j0 >> 6) & (NH - 1);
    const int bhh = b * NH + h;
#pragma unroll
    for (int tn = 0; tn < 4; tn++) {
        const int d = warp_n * 32 + tn * 8 + 2 * (lane & 3);
        const float bv0 = bias[j0 + d], bv1 = bias[j0 + d + 1];
#pragma unroll
        for (int tm = 0; tm < 2; tm++) {
            const int n = m0 + warp_m * 32 + tm * 16 + (lane >> 2);
            float v0 = acc[tm][tn][0] + bv0, v1 = acc[tm][tn][1] + bv1;
            float v2 = acc[tm][tn][2] + bv0, v3 = acc[tm][tn][3] + bv1;
            if (s == 2) {
                size_t a0 = ((size_t)bhh * NTOK + n) * HD + d;
                *(uint32_t*)&g_v[a0] = pack_hh(v0, v1);
                *(uint32_t*)&g_v[a0 + 8 * HD] = pack_hh(v2, v3);
            } else {
                if (s == 0) { v0 *= ATT_SCALE; v1 *= ATT_SCALE; v2 *= ATT_SCALE; v3 *= ATT_SCALE; }
                __half* dq = (s == 0) ? g_q : g_k;
                const size_t b0 = ((size_t)bhh * HD + d) * NTOK;
                const size_t b1 = b0 + NTOK;
                dq[b0 + n]     = __float2half(v0);
                dq[b1 + n]     = __float2half(v1);
                dq[b0 + n + 8] = __float2half(v2);
                dq[b1 + n + 8] = __float2half(v3);
            }
        }
    }
}

// ===================== Kernel 2: Flash attention (fp16) =====================
// smem: Q [64][256B] at 0 (16 KB); stage s at 16384 + s*32768:
//   K [64][256B] +0, V [128][128B] +16384.  Total 80 KB.
#define ATTN_SMEM 81920

__device__ __forceinline__ void attn_copy_stage(
    uint32_t St, const __half* k_, const __half* v_, int n0, int tid)
{
#pragma unroll
    for (int i = 0; i < 4; i++) {
        int q = tid + i * 256, k = q >> 4, c = q & 15;     // K: 64 rows x 16
        uint32_t off = k * 256 + ((c ^ (k & 7)) << 4);
        cp16(St + off, k_ + (size_t)k * NTOK + n0 + c * 8);
    }
#pragma unroll
    for (int i = 0; i < 4; i++) {
        int q = tid + i * 256, k = q >> 3, c = q & 7;      // V: 128 rows x 8
        uint32_t off = k * 128 + ((c ^ (k & 7)) << 4);
        cp16(St + 16384 + off, v_ + (size_t)(n0 + k) * HD + c * 8);
    }
}

__global__ void __launch_bounds__(256) attn_hmma_kernel()
{
    extern __shared__ char sm[];
    const uint32_t Qb = smem_u32(sm);

    const int tid = threadIdx.x, lane = tid & 31, w = tid >> 5;
    const int g = lane >> 3, r8 = lane & 7;
    const int bh = blockIdx.x;
    const int m0 = blockIdx.y * 128;

    const __half* qp = g_q + (size_t)bh * HD * NTOK;
    const __half* kp = g_k + (size_t)bh * HD * NTOK;
    const __half* vp = g_v + (size_t)bh * NTOK * HD;

    // prefetch KV block 0 while loading Q
    attn_copy_stage(Qb + 16384, kp, vp, 0, tid);
    CP_COMMIT();

#pragma unroll
    for (int i = 0; i < 4; i++) {
        int q = tid + i * 256, k = q >> 4, c = q & 15;
        uint32_t off = k * 256 + ((c ^ (k & 7)) << 4);
        *(int4*)(sm + off) = *(const int4*)(qp + (size_t)k * NTOK + m0 + c * 8);
    }
    __syncthreads();

    uint32_t aq[4][4];
    {
        const int ccA = 2 * w + (g & 1);
#pragma unroll
        for (int ks = 0; ks < 4; ks++) {
            const int klA = ks * 16 + ((g >> 1) << 3) + r8;
            ldsm4t(aq[ks], Qb + klA * 256 + ((ccA ^ (klA & 7)) << 4));
        }
    }

    float mr0 = -1e30f, mr1 = -1e30f, l0 = 0.f, l1 = 0.f;
    float of[8][4];
#pragma unroll
    for (int tn = 0; tn < 8; tn++)
#pragma unroll
        for (int q = 0; q < 4; q++) of[tn][q] = 0.f;

    for (int nb = 0; nb < 8; nb++) {
        const uint32_t St = Qb + 16384 + (nb & 1) * 32768;
        if (nb < 7) {
            attn_copy_stage(Qb + 16384 + ((nb + 1) & 1) * 32768,
                            kp, vp, (nb + 1) * 128, tid);
            CP_COMMIT();
            CP_WAIT1();
        } else {
            CP_WAIT0();
        }
        __syncthreads();

        const uint32_t Kb = St, Vb = St + 16384;

        float sf[16][4];
#pragma unroll
        for (int t = 0; t < 16; t++)
#pragma unroll
            for (int q = 0; q < 4; q++) sf[t][q] = 0.f;

#pragma unroll
        for (int ks = 0; ks < 4; ks++) {
            const int klB = ks * 16 + ((g & 1) << 3) + r8;
#pragma unroll
            for (int tp = 0; tp < 8; tp++) {
                uint32_t bk[4];
                const int cc = tp * 2 + (g >> 1);
                ldsm4t(bk, Kb + klB * 256 + ((cc ^ (klB & 7)) << 4));
                mma16816(sf[2 * tp],     aq[ks], &bk[0]);
                mma16816(sf[2 * tp + 1], aq[ks], &bk[2]);
            }
        }

        float mx0 = -1e30f, mx1 = -1e30f;
#pragma unroll
        for (int t = 0; t < 16; t++) {
            mx0 = fmaxf(mx0, fmaxf(sf[t][0], sf[t][1]));
            mx1 = fmaxf(mx1, fmaxf(sf[t][2], sf[t][3]));
        }
        mx0 = fmaxf(mx0, __shfl_xor_sync(0xffffffffu, mx0, 1));
        mx0 = fmaxf(mx0, __shfl_xor_sync(0xffffffffu, mx0, 2));
        mx1 = fmaxf(mx1, __shfl_xor_sync(0xffffffffu, mx1, 1));
        mx1 = fmaxf(mx1, __shfl_xor_sync(0xffffffffu, mx1, 2));
        const float nm0 = fmaxf(mr0, mx0), nm1 = fmaxf(mr1, mx1);
        const float a0 = __expf(mr0 - nm0), a1 = __expf(mr1 - nm1);
        mr0 = nm0; mr1 = nm1;
        float rs0 = 0.f, rs1 = 0.f;
#pragma unroll
        for (int t = 0; t < 16; t++) {
            sf[t][0] = __expf(sf[t][0] - nm0);
            sf[t][1] = __expf(sf[t][1] - nm0);
            sf[t][2] = __expf(sf[t][2] - nm1);
            sf[t][3] = __expf(sf[t][3] - nm1);
            rs0 += sf[t][0] + sf[t][1];
            rs1 += sf[t][2] + sf[t][3];
        }
        rs0 += __shfl_xor_sync(0xffffffffu, rs0, 1);
        rs0 += __shfl_xor_sync(0xffffffffu, rs0, 2);
        rs1 += __shfl_xor_sync(0xffffffffu, rs1, 1);
        rs1 += __shfl_xor_sync(0xffffffffu, rs1, 2);
        l0 = l0 * a0 + rs0;
        l1 = l1 * a1 + rs1;
#pragma unroll
        for (int tn = 0; tn < 8; tn++) {
            of[tn][0] *= a0; of[tn][1] *= a0;
            of[tn][2] *= a1; of[tn][3] *= a1;
        }

#pragma unroll
        for (int ks = 0; ks < 8; ks++) {
            uint32_t pa[4];
            pa[0] = pack_hh(sf[2 * ks][0],     sf[2 * ks][1]);
            pa[1] = pack_hh(sf[2 * ks][2],     sf[2 * ks][3]);
            pa[2] = pack_hh(sf[2 * ks + 1][0], sf[2 * ks + 1][1]);
            pa[3] = pack_hh(sf[2 * ks + 1][2], sf[2 * ks + 1][3]);
            const int klV = ks * 16 + ((g & 1) << 3) + r8;
#pragma unroll
            for (int tp = 0; tp < 4; tp++) {
                uint32_t bv[4];
                const int cc = tp * 2 + (g >> 1);
                ldsm4t(bv, Vb + klV * 128 + ((cc ^ (klV & 7)) << 4));
                mma16816(of[2 * tp],     pa, &bv[0]);
                mma16816(of[2 * tp + 1], pa, &bv[2]);
            }
        }
        __syncthreads();
    }

    // ---- normalize + write O^T fp16 to g_o [b][c][n] ----
    const int b = bh >> 3, h = bh & 7;
    const float inv0 = 1.f / l0, inv1 = 1.f / l1;
    const int r = w * 16 + (lane >> 2);
    const size_t cbase = ((size_t)b * CH + h * HD) * NTOK;
    const int n = m0 + r;
#pragma unroll
    for (int tn = 0; tn < 8; tn++) {
        const int d = tn * 8 + 2 * (lane & 3);
        const size_t c0 = cbase + (size_t)d * NTOK;
        const size_t c1 = c0 + NTOK;
        g_o[c0 + n]     = __float2half(of[tn][0] * inv0);
        g_o[c1 + n]     = __float2half(of[tn][1] * inv0);
        g_o[c0 + n + 8] = __float2half(of[tn][2] * inv1);
        g_o[c1 + n + 8] = __float2half(of[tn][3] * inv1);
    }
}

// ===================== Kernel 3: Proj GEMM =================================
__global__ void __launch_bounds__(256, 2) proj_hmma_kernel(
    const float* __restrict__ bias, float* __restrict__ out)
{
    extern __shared__ char sm[];
    const int tid = threadIdx.x, lane = tid & 31, wid = tid >> 5;
    const int warp_m = wid & 3, warp_n = wid >> 2;
    const int j0 = blockIdx.x * 64, m0 = blockIdx.y * 128, b = blockIdx.z;

    float acc[2][4][4];
#pragma unroll
    for (int tm = 0; tm < 2; tm++)
#pragma unroll
        for (int tn = 0; tn < 4; tn++)
#pragma unroll
            for (int q = 0; q < 4; q++) acc[tm][tn][q] = 0.f;

    gemm_pipeline(sm, g_o + (size_t)b * CH * NTOK + m0,
                  g_pw + j0, CH, acc, tid, lane, warp_m, warp_n);

    float* ob = out + (size_t)b * CH * NTOK;
#pragma unroll
    for (int tn = 0; tn < 4; tn++) {
        const int j = j0 + warp_n * 32 + tn * 8 + 2 * (lane & 3);
        const float bv0 = bias[j], bv1 = bias[j + 1];
        float* p0 = ob + (size_t)j * NTOK;
        float* p1 = p0 + NTOK;
#pragma unroll
        for (int tm = 0; tm < 2; tm++) {
            const int n = m0 + warp_m * 32 + tm * 16 + (lane >> 2);
            p0[n]     = acc[tm][tn][0] + bv0;
            p1[n]     = acc[tm][tn][1] + bv1;
            p0[n + 8] = acc[tm][tn][2] + bv0;
            p1[n + 8] = acc[tm][tn][3] + bv1;
        }
    }
}

// ---------------------------------------------------------------------------
extern "C" void kernel_launch(void* const* d_in, const int* in_sizes, int n_in,
                              void* d_out, int out_size)
{
    const float* x      = (const float*)d_in[0];
    const float* w_qkv  = (const float*)d_in[1];
    const float* b_qkv  = (const float*)d_in[2];
    const float* w_proj = (const float*)d_in[3];
    const float* b_proj = (const float*)d_in[4];
    float* out = (float*)d_out;

    cudaFuncSetAttribute(qkv_hmma_kernel,
                         cudaFuncAttributeMaxDynamicSharedMemorySize, GEMM_SMEM);
    cudaFuncSetAttribute(attn_hmma_kernel,
                         cudaFuncAttributeMaxDynamicSharedMemorySize, ATTN_SMEM);
    cudaFuncSetAttribute(proj_hmma_kernel,
                         cudaFuncAttributeMaxDynamicSharedMemorySize, GEMM_SMEM);

    prep_x_kernel<<<(BATCH * CH * NTOK / 4) / 256, 256>>>((const float4*)x);
    prep_w_kernel<<<(CH * TC / 4) / 256, 256>>>((const float4*)w_qkv);
    prep_pw_kernel<<<(CH * CH / 4) / 256, 256>>>((const float4*)w_proj);
    qkv_hmma_kernel<<<dim3(TC / 64, NTOK / 128, BATCH), 256, GEMM_SMEM>>>(b_qkv);
    attn_hmma_kernel<<<dim3(BATCH * NH, NTOK / 128), 256, ATTN_SMEM>>>();
    proj_hmma_kernel<<<dim3(CH / 64, NTOK / 128, BATCH), 256, GEMM_SMEM>>>(b_proj, out);
}